// round 1
// baseline (speedup 1.0000x reference)
#include <cuda_runtime.h>

#define BATCH 256
#define ISZ   512
#define STEPS 256
#define HID   512
#define GH    1536          // 3*HID
#define NCTA  128           // persistent recurrence CTAs (<=148, all resident)

// ---------------- scratch (static device allocations only) ----------------
__device__ float g_xt[(size_t)STEPS * BATCH * ISZ];   // [s*B+b][i]   134MB
__device__ float g_wt[(size_t)ISZ * GH];              // [i][g]       3MB
__device__ float g_gi[(size_t)STEPS * BATCH * GH];    // [s*B+b][g]   403MB
__device__ float g_h[2][BATCH * HID];                 // double buffer
__device__ unsigned g_bar_cnt;
__device__ volatile unsigned g_bar_gen;

// ---------------- transpose Wih [GH,ISZ] -> g_wt [ISZ,GH] ----------------
__global__ void k_wt_transpose(const float* __restrict__ wih) {
    __shared__ float tile[32][33];
    int k0 = blockIdx.x * 32;   // ISZ tiles
    int n0 = blockIdx.y * 32;   // GH tiles
    int tx = threadIdx.x, ty = threadIdx.y;
    #pragma unroll
    for (int j = 0; j < 4; ++j)
        tile[ty + 8 * j][tx] = wih[(size_t)(n0 + ty + 8 * j) * ISZ + k0 + tx];
    __syncthreads();
    #pragma unroll
    for (int j = 0; j < 4; ++j)
        g_wt[(size_t)(k0 + ty + 8 * j) * GH + n0 + tx] = tile[tx][ty + 8 * j];
}

// ---------------- transpose x [B][I][S] -> g_xt [(s*B+b)][i] ----------------
__global__ void k_x_transpose(const float* __restrict__ x) {
    __shared__ float tile[32][33];
    int s0 = blockIdx.x * 32;
    int i0 = blockIdx.y * 32;
    int b  = blockIdx.z;
    int tx = threadIdx.x, ty = threadIdx.y;
    #pragma unroll
    for (int j = 0; j < 4; ++j)
        tile[ty + 8 * j][tx] = x[((size_t)b * ISZ + i0 + ty + 8 * j) * STEPS + s0 + tx];
    __syncthreads();
    #pragma unroll
    for (int j = 0; j < 4; ++j) {
        int s = s0 + ty + 8 * j;
        g_xt[((size_t)s * BATCH + b) * ISZ + i0 + tx] = tile[tx][ty + 8 * j];
    }
}

// ---------------- fp32 SGEMM: g_gi = g_xt(65536x512) * g_wt(512x1536) + bias_ih
// 128x128 block tile, BK=8, 256 threads, 8x8 per-thread register tile.
__global__ void __launch_bounds__(256) k_sgemm_gi(const float* __restrict__ bias_ih) {
    __shared__ float As[8][128];
    __shared__ float Bs[8][128];
    const int m0 = blockIdx.y * 128;
    const int n0 = blockIdx.x * 128;
    const int tid = threadIdx.x;
    const int tr = tid >> 4;          // 0..15
    const int tc = tid & 15;          // 0..15
    const int ar = tid >> 1;          // A load row 0..127
    const int akq = tid & 1;          // A load float4 index in k
    const int bn = tid & 31;          // B load col quad 0..31
    const int bk = tid >> 5;          // B load k row 0..7

    float acc[8][8];
    #pragma unroll
    for (int i = 0; i < 8; ++i)
        #pragma unroll
        for (int j = 0; j < 8; ++j) acc[i][j] = 0.f;

    for (int k0 = 0; k0 < ISZ; k0 += 8) {
        float4 av = *(const float4*)(g_xt + (size_t)(m0 + ar) * ISZ + k0 + akq * 4);
        float4 bv = *(const float4*)(g_wt + (size_t)(k0 + bk) * GH + n0 + bn * 4);
        As[akq * 4 + 0][ar] = av.x;
        As[akq * 4 + 1][ar] = av.y;
        As[akq * 4 + 2][ar] = av.z;
        As[akq * 4 + 3][ar] = av.w;
        *(float4*)(&Bs[bk][bn * 4]) = bv;
        __syncthreads();
        #pragma unroll
        for (int kk = 0; kk < 8; ++kk) {
            float a[8], b[8];
            *(float4*)(a)     = *(const float4*)(&As[kk][tr * 8]);
            *(float4*)(a + 4) = *(const float4*)(&As[kk][tr * 8 + 4]);
            *(float4*)(b)     = *(const float4*)(&Bs[kk][tc * 8]);
            *(float4*)(b + 4) = *(const float4*)(&Bs[kk][tc * 8 + 4]);
            #pragma unroll
            for (int i = 0; i < 8; ++i)
                #pragma unroll
                for (int j = 0; j < 8; ++j)
                    acc[i][j] += a[i] * b[j];
        }
        __syncthreads();
    }
    // epilogue: +bias_ih, store
    #pragma unroll
    for (int i = 0; i < 8; ++i) {
        size_t row = (size_t)(m0 + tr * 8 + i) * GH;
        #pragma unroll
        for (int j = 0; j < 8; j += 4) {
            float4 bb = *(const float4*)(bias_ih + n0 + tc * 8 + j);
            float4 v;
            v.x = acc[i][j + 0] + bb.x;
            v.y = acc[i][j + 1] + bb.y;
            v.z = acc[i][j + 2] + bb.z;
            v.w = acc[i][j + 3] + bb.w;
            *(float4*)(g_gi + row + n0 + tc * 8 + j) = v;
        }
    }
}

// ---------------- persistent GRU recurrence ----------------
// 128 CTAs x 256 threads. CTA c owns hidden cols [4c,4c+4) -> 12 Whh rows in smem.
// Per step: stream full h (L2) in 4 tiles of 64 rows, GEMM slice, gates, write h slice,
// grid barrier.

__device__ __forceinline__ void gridbar(unsigned target) {
    __syncthreads();
    if (threadIdx.x == 0) {
        __threadfence();
        unsigned a = atomicAdd(&g_bar_cnt, 1u);
        if (a == NCTA - 1) {
            atomicExch(&g_bar_cnt, 0u);
            __threadfence();
            g_bar_gen = target;
        } else {
            while ((int)(g_bar_gen - target) < 0) __nanosleep(64);
        }
        __threadfence();
    }
    __syncthreads();
}

#define HS_STRIDE 516
#define WS_STRIDE 516
// smem floats: Hs 64*516 + Ws 12*516 + part 4*64*12 + sB 16
#define REC_SMEM_FLOATS (64 * HS_STRIDE + 12 * WS_STRIDE + 4 * 64 * 12 + 16)
#define REC_SMEM_BYTES  (REC_SMEM_FLOATS * 4)

__global__ void __launch_bounds__(256, 1) k_gru_recur(
    const float* __restrict__ whh, const float* __restrict__ bhh,
    float* __restrict__ out)
{
    extern __shared__ float sm[];
    float* Hs   = sm;                                  // [64][516]
    float* Ws   = sm + 64 * HS_STRIDE;                 // [12][516]  row = gate*4 + q
    float* part = Ws + 12 * WS_STRIDE;                 // [4ks][64][12]
    float* sB   = part + 4 * 64 * 12;                  // [12]

    const int c = blockIdx.x;
    const int tid = threadIdx.x;

    // load Whh slice (12 rows of 512) into smem, padded stride
    for (int idx = tid * 4; idx < 12 * 512; idx += 256 * 4) {
        int r = idx >> 9;          // 0..11
        int k = idx & 511;
        int g = r >> 2, q = r & 3;
        int grow = g * HID + c * 4 + q;
        float4 v = *(const float4*)(whh + (size_t)grow * HID + k);
        *(float4*)(Ws + r * WS_STRIDE + k) = v;
    }
    if (tid < 12) {
        int g = tid >> 2, q = tid & 3;
        sB[tid] = bhh[g * HID + c * 4 + q];
    }
    // zero h buffer 0 (each CTA zeros a disjoint 1024-float chunk)
    {
        float4 z = make_float4(0.f, 0.f, 0.f, 0.f);
        *(float4*)(&g_h[0][(c * 256 + tid) * 4]) = z;
    }

    // read barrier generation base BEFORE first arrival (safe: release of bar#1
    // needs all 128 arrivals, each preceded by its own base read)
    unsigned base = g_bar_gen;
    gridbar(base + 1);

    const int b_g = tid & 15;          // 16 b-groups
    const int q   = (tid >> 4) & 3;    // hidden col within CTA
    const int ks  = tid >> 6;          // 4-way k split
    const int q2  = tid & 3;           // gate-phase mapping
    const int bl2 = tid >> 2;

    const float* wr = Ws + (0 * 4 + q) * WS_STRIDE;
    const float* wz = Ws + (1 * 4 + q) * WS_STRIDE;
    const float* wn = Ws + (2 * 4 + q) * WS_STRIDE;
    const int k0 = ks * 128;

    for (int s = 0; s < STEPS; ++s) {
        const float* hin = g_h[s & 1];
        float* hout = g_h[(s + 1) & 1];

        for (int bt = 0; bt < 4; ++bt) {
            // load 64x512 h tile (L2 via ldcg: bypass stale L1 across steps)
            for (int i = tid; i < 64 * 128; i += 256) {
                int row = i >> 7, col = i & 127;
                float4 v = __ldcg((const float4*)(hin + (size_t)(bt * 64 + row) * HID + col * 4));
                *(float4*)(Hs + row * HS_STRIDE + col * 4) = v;
            }
            __syncthreads();

            float accr[4] = {0.f, 0.f, 0.f, 0.f};
            float accz[4] = {0.f, 0.f, 0.f, 0.f};
            float accn[4] = {0.f, 0.f, 0.f, 0.f};
            const float* hp0 = Hs + (b_g + 0)  * HS_STRIDE;
            const float* hp1 = Hs + (b_g + 16) * HS_STRIDE;
            const float* hp2 = Hs + (b_g + 32) * HS_STRIDE;
            const float* hp3 = Hs + (b_g + 48) * HS_STRIDE;

            #pragma unroll 2
            for (int k = k0; k < k0 + 128; k += 4) {
                float4 w4r = *(const float4*)(wr + k);
                float4 w4z = *(const float4*)(wz + k);
                float4 w4n = *(const float4*)(wn + k);
                float4 hv;
                hv = *(const float4*)(hp0 + k);
                accr[0] += hv.x*w4r.x + hv.y*w4r.y + hv.z*w4r.z + hv.w*w4r.w;
                accz[0] += hv.x*w4z.x + hv.y*w4z.y + hv.z*w4z.z + hv.w*w4z.w;
                accn[0] += hv.x*w4n.x + hv.y*w4n.y + hv.z*w4n.z + hv.w*w4n.w;
                hv = *(const float4*)(hp1 + k);
                accr[1] += hv.x*w4r.x + hv.y*w4r.y + hv.z*w4r.z + hv.w*w4r.w;
                accz[1] += hv.x*w4z.x + hv.y*w4z.y + hv.z*w4z.z + hv.w*w4z.w;
                accn[1] += hv.x*w4n.x + hv.y*w4n.y + hv.z*w4n.z + hv.w*w4n.w;
                hv = *(const float4*)(hp2 + k);
                accr[2] += hv.x*w4r.x + hv.y*w4r.y + hv.z*w4r.z + hv.w*w4r.w;
                accz[2] += hv.x*w4z.x + hv.y*w4z.y + hv.z*w4z.z + hv.w*w4z.w;
                accn[2] += hv.x*w4n.x + hv.y*w4n.y + hv.z*w4n.z + hv.w*w4n.w;
                hv = *(const float4*)(hp3 + k);
                accr[3] += hv.x*w4r.x + hv.y*w4r.y + hv.z*w4r.z + hv.w*w4r.w;
                accz[3] += hv.x*w4z.x + hv.y*w4z.y + hv.z*w4z.z + hv.w*w4z.w;
                accn[3] += hv.x*w4n.x + hv.y*w4n.y + hv.z*w4n.z + hv.w*w4n.w;
            }

            #pragma unroll
            for (int j = 0; j < 4; ++j) {
                int b_l = b_g + 16 * j;
                float* p = part + (ks * 64 + b_l) * 12;
                p[0 + q] = accr[j];
                p[4 + q] = accz[j];
                p[8 + q] = accn[j];
            }
            __syncthreads();

            // gate phase: one (b,hidden-col) per thread
            {
                float ar = 0.f, az = 0.f, an = 0.f;
                #pragma unroll
                for (int kq = 0; kq < 4; ++kq) {
                    const float* p = part + (kq * 64 + bl2) * 12;
                    ar += p[0 + q2];
                    az += p[4 + q2];
                    an += p[8 + q2];
                }
                int bglob = bt * 64 + bl2;
                size_t gib = ((size_t)s * BATCH + bglob) * GH + c * 4 + q2;
                float gr = __ldcg(g_gi + gib);
                float gz = __ldcg(g_gi + gib + HID);
                float gn = __ldcg(g_gi + gib + 2 * HID);
                float rg = 1.f / (1.f + expf(-(gr + ar + sB[0 + q2])));
                float zg = 1.f / (1.f + expf(-(gz + az + sB[4 + q2])));
                float ng = tanhf(gn + rg * (an + sB[8 + q2]));
                float hold = Hs[bl2 * HS_STRIDE + c * 4 + q2];
                float hnew = (1.f - zg) * ng + zg * hold;
                hout[(size_t)bglob * HID + c * 4 + q2] = hnew;
                if (s == STEPS - 1)
                    out[(size_t)bglob * HID + c * 4 + q2] = hnew;
            }
            __syncthreads();   // protect Hs before next tile load
        }
        gridbar(base + 2 + s);
    }
}

// ---------------- launcher ----------------
extern "C" void kernel_launch(void* const* d_in, const int* in_sizes, int n_in,
                              void* d_out, int out_size) {
    const float* x   = (const float*)d_in[0];
    const float* wih = (const float*)d_in[1];
    const float* whh = (const float*)d_in[2];
    const float* bih = (const float*)d_in[3];
    const float* bhh = (const float*)d_in[4];
    float* out = (float*)d_out;

    cudaFuncSetAttribute(k_gru_recur, cudaFuncAttributeMaxDynamicSharedMemorySize,
                         REC_SMEM_BYTES);

    k_wt_transpose<<<dim3(ISZ / 32, GH / 32), dim3(32, 8)>>>(wih);
    k_x_transpose<<<dim3(STEPS / 32, ISZ / 32, BATCH), dim3(32, 8)>>>(x);
    k_sgemm_gi<<<dim3(GH / 128, (STEPS * BATCH) / 128), 256>>>(bih);
    k_gru_recur<<<NCTA, 256, REC_SMEM_BYTES>>>(whh, bhh, out);
}

// round 3
// speedup vs baseline: 1.2376x; 1.2376x over previous
#include <cuda_runtime.h>
#include <cuda_bf16.h>
#include <cstdint>

#define BATCH 256
#define ISZ   512
#define STEPS 256
#define HID   512
#define GH    1536
#define NCTA  128
#define MROWS (STEPS * BATCH)     // 65536

// ---------------- scratch ----------------
__device__ __nv_bfloat16 g_xhi[(size_t)MROWS * ISZ];
__device__ __nv_bfloat16 g_xlo[(size_t)MROWS * ISZ];
__device__ __nv_bfloat16 g_whi[(size_t)GH * ISZ];
__device__ __nv_bfloat16 g_wlo[(size_t)GH * ISZ];
__device__ float g_gi[(size_t)MROWS * GH];
__device__ float g_h[2][BATCH * HID];
__device__ unsigned g_bar_cnt;
__device__ volatile unsigned g_bar_gen;

// ---------------- helpers ----------------
__device__ __forceinline__ uint32_t smem_to_u32(const void* p) {
    uint32_t a;
    asm("{ .reg .u64 t; cvta.to.shared.u64 t, %1; cvt.u32.u64 %0, t; }" : "=r"(a) : "l"(p));
    return a;
}
__device__ __forceinline__ void cp16(uint32_t dst, const void* src) {
    asm volatile("cp.async.cg.shared.global [%0], [%1], 16;" :: "r"(dst), "l"(src));
}
#define CP_COMMIT() asm volatile("cp.async.commit_group;" ::: "memory")
#define CP_WAIT(n)  asm volatile("cp.async.wait_group %0;" :: "n"(n) : "memory")

__device__ __forceinline__ void ldsm_x4(uint32_t addr, uint32_t r[4]) {
    asm volatile("ldmatrix.sync.aligned.m8n8.x4.shared.b16 {%0,%1,%2,%3}, [%4];"
                 : "=r"(r[0]), "=r"(r[1]), "=r"(r[2]), "=r"(r[3]) : "r"(addr));
}
__device__ __forceinline__ void mma_bf16(float d[4], const uint32_t a[4], const uint32_t b[2]) {
    asm volatile("mma.sync.aligned.m16n8k16.row.col.f32.bf16.bf16.f32 "
                 "{%0,%1,%2,%3}, {%4,%5,%6,%7}, {%8,%9}, {%0,%1,%2,%3};"
                 : "+f"(d[0]), "+f"(d[1]), "+f"(d[2]), "+f"(d[3])
                 : "r"(a[0]), "r"(a[1]), "r"(a[2]), "r"(a[3]), "r"(b[0]), "r"(b[1]));
}
__device__ __forceinline__ unsigned long long fma2(unsigned long long a,
                                                   unsigned long long b,
                                                   unsigned long long c) {
    unsigned long long d;
    asm("fma.rn.f32x2 %0, %1, %2, %3;" : "=l"(d) : "l"(a), "l"(b), "l"(c));
    return d;
}
__device__ __forceinline__ void split_bf16(float v, __nv_bfloat16& hi, __nv_bfloat16& lo) {
    hi = __float2bfloat16_rn(v);
    lo = __float2bfloat16_rn(v - __bfloat162float(hi));
}

// ---------------- Wih -> bf16 hi/lo ----------------
__global__ void k_w_convert(const float* __restrict__ wih) {
    size_t i = (size_t)blockIdx.x * 1024 + threadIdx.x * 4;
    #pragma unroll
    for (int j = 0; j < 4; ++j) {
        float v = wih[i + j];
        split_bf16(v, g_whi[i + j], g_wlo[i + j]);
    }
}

// ---------------- x [B][I][S] -> g_xhi/g_xlo [(s*B+b)][i] bf16 ----------------
__global__ void k_x_transpose(const float* __restrict__ x) {
    __shared__ float tile[32][33];
    int s0 = blockIdx.x * 32;
    int i0 = blockIdx.y * 32;
    int b  = blockIdx.z;
    int tx = threadIdx.x, ty = threadIdx.y;
    #pragma unroll
    for (int j = 0; j < 4; ++j)
        tile[ty + 8 * j][tx] = x[((size_t)b * ISZ + i0 + ty + 8 * j) * STEPS + s0 + tx];
    __syncthreads();
    #pragma unroll
    for (int j = 0; j < 4; ++j) {
        int s = s0 + ty + 8 * j;
        float v = tile[tx][ty + 8 * j];
        size_t o = ((size_t)s * BATCH + b) * ISZ + i0 + tx;
        split_bf16(v, g_xhi[o], g_xlo[o]);
    }
}

// ---------------- HMMA GEMM: gi = x_split @ Wih_split^T + bias_ih ----------------
// CTA tile 128x128, K-chunk 64 double-buffered via cp.async.
// 8 warps: wm = wid&3 (4 m-splits of 32), wn = wid>>2 (2 n-splits of 64).
// Per warp: 2 m-tiles (16) x 8 n-tiles (8). 3-MMA hi/lo split per fragment.
#define SA 72                      // smem row stride in bf16 (144 B)
#define ATILE_B (128 * SA * 2)     // 18432 B per tile
#define GEMM_SMEM (2 * 4 * ATILE_B)  // 147456

__device__ __forceinline__ void gi_issue_load(uint32_t sb, int tid, int m0, int n0,
                                              int chunk, int buf) {
    const int k0 = chunk * 64;
    const __nv_bfloat16* srcs[4] = {g_xhi, g_xlo, g_whi, g_wlo};
    const int rowbase[4] = {m0, m0, n0, n0};
    #pragma unroll
    for (int t = 0; t < 4; ++t) {
        const __nv_bfloat16* src = srcs[t];
        uint32_t dst0 = sb + buf * 4 * ATILE_B + t * ATILE_B;
        #pragma unroll
        for (int i = 0; i < 4; ++i) {
            int lin = tid + 256 * i;       // 1024 16B chunks per tile
            int row = lin >> 3;
            int cq  = lin & 7;
            cp16(dst0 + row * (SA * 2) + cq * 16,
                 src + (size_t)(rowbase[t] + row) * ISZ + k0 + cq * 8);
        }
    }
}

__global__ void __launch_bounds__(256, 1) k_gemm_gi(const float* __restrict__ bias_ih) {
    extern __shared__ char smem[];
    uint32_t sb = smem_to_u32(smem);
    const int tid = threadIdx.x;
    const int lane = tid & 31;
    const int wid = tid >> 5;
    const int wm = wid & 3;
    const int wn = wid >> 2;
    const int m0 = blockIdx.y * 128;
    const int n0 = blockIdx.x * 128;

    // ldmatrix per-lane address components
    const int t4 = lane >> 3;
    const int arow = (t4 & 1) * 8 + (lane & 7);   // within m16
    const int acol = (t4 >> 1) * 8;               // k half
    const int brow = (t4 >> 1) * 8 + (lane & 7);  // within n16 pair
    const int bcol = (t4 & 1) * 8;                // k half

    float acc[2][8][4];
    #pragma unroll
    for (int i = 0; i < 2; ++i)
        #pragma unroll
        for (int j = 0; j < 8; ++j)
            #pragma unroll
            for (int v = 0; v < 4; ++v) acc[i][j][v] = 0.f;

    gi_issue_load(sb, tid, m0, n0, 0, 0);
    CP_COMMIT();

    for (int c = 0; c < 8; ++c) {
        if (c < 7) {
            gi_issue_load(sb, tid, m0, n0, c + 1, (c + 1) & 1);
            CP_COMMIT();
            CP_WAIT(1);
        } else {
            CP_WAIT(0);
        }
        __syncthreads();
        const int buf = c & 1;
        const uint32_t bufb = sb + buf * 4 * ATILE_B;

        #pragma unroll
        for (int kk = 0; kk < 64; kk += 16) {
            uint32_t Ah[2][4], Al[2][4], Bh[8][2], Bl[8][2];
            #pragma unroll
            for (int mt = 0; mt < 2; ++mt) {
                uint32_t r = (wm * 32 + mt * 16 + arow) * (SA * 2) + (kk + acol) * 2;
                ldsm_x4(bufb + 0 * ATILE_B + r, Ah[mt]);
                ldsm_x4(bufb + 1 * ATILE_B + r, Al[mt]);
            }
            #pragma unroll
            for (int pt = 0; pt < 4; ++pt) {
                uint32_t r = (wn * 64 + pt * 16 + brow) * (SA * 2) + (kk + bcol) * 2;
                uint32_t q[4];
                ldsm_x4(bufb + 2 * ATILE_B + r, q);
                Bh[2 * pt][0] = q[0]; Bh[2 * pt][1] = q[1];
                Bh[2 * pt + 1][0] = q[2]; Bh[2 * pt + 1][1] = q[3];
                ldsm_x4(bufb + 3 * ATILE_B + r, q);
                Bl[2 * pt][0] = q[0]; Bl[2 * pt][1] = q[1];
                Bl[2 * pt + 1][0] = q[2]; Bl[2 * pt + 1][1] = q[3];
            }
            #pragma unroll
            for (int mt = 0; mt < 2; ++mt)
                #pragma unroll
                for (int nt = 0; nt < 8; ++nt) {
                    mma_bf16(acc[mt][nt], Ah[mt], Bh[nt]);
                    mma_bf16(acc[mt][nt], Ah[mt], Bl[nt]);
                    mma_bf16(acc[mt][nt], Al[mt], Bh[nt]);
                }
        }
        __syncthreads();
    }

    // epilogue: +bias, store
    #pragma unroll
    for (int nt = 0; nt < 8; ++nt) {
        int n_base = n0 + wn * 64 + nt * 8 + (lane & 3) * 2;
        float2 bb = *(const float2*)(bias_ih + n_base);
        #pragma unroll
        for (int mt = 0; mt < 2; ++mt) {
            int m_base = m0 + wm * 32 + mt * 16 + (lane >> 2);
            float2 v0, v1;
            v0.x = acc[mt][nt][0] + bb.x;
            v0.y = acc[mt][nt][1] + bb.y;
            v1.x = acc[mt][nt][2] + bb.x;
            v1.y = acc[mt][nt][3] + bb.y;
            *(float2*)(g_gi + (size_t)m_base * GH + n_base) = v0;
            *(float2*)(g_gi + (size_t)(m_base + 8) * GH + n_base) = v1;
        }
    }
}

// ---------------- persistent GRU recurrence (f32x2, 8 b/thread, 8-way k-split) -------
__device__ __forceinline__ void gridbar(unsigned target) {
    __syncthreads();
    if (threadIdx.x == 0) {
        __threadfence();
        unsigned a = atomicAdd(&g_bar_cnt, 1u);
        if (a == NCTA - 1) {
            atomicExch(&g_bar_cnt, 0u);
            __threadfence();
            g_bar_gen = target;
        } else {
            while ((int)(g_bar_gen - target) < 0) __nanosleep(64);
        }
        __threadfence();
    }
    __syncthreads();
}

#define HS_STRIDE 516
#define WS_STRIDE 516
#define REC_SMEM_FLOATS (64 * HS_STRIDE + 12 * WS_STRIDE + 8 * 64 * 12 + 16)
#define REC_SMEM_BYTES  (REC_SMEM_FLOATS * 4)

__global__ void __launch_bounds__(256, 1) k_gru_recur(
    const float* __restrict__ whh, const float* __restrict__ bhh,
    float* __restrict__ out)
{
    extern __shared__ float sm[];
    float* Hs   = sm;                              // [64][516]
    float* Ws   = sm + 64 * HS_STRIDE;             // [12][516]  row = gate*4 + q
    float* part = Ws + 12 * WS_STRIDE;             // [8 ks][64][12]
    float* sB   = part + 8 * 64 * 12;              // [12]

    const int c = blockIdx.x;
    const int tid = threadIdx.x;

    for (int idx = tid * 4; idx < 12 * 512; idx += 256 * 4) {
        int r = idx >> 9;
        int k = idx & 511;
        int g = r >> 2, q = r & 3;
        int grow = g * HID + c * 4 + q;
        float4 v = *(const float4*)(whh + (size_t)grow * HID + k);
        *(float4*)(Ws + r * WS_STRIDE + k) = v;
    }
    if (tid < 12) {
        int g = tid >> 2, q = tid & 3;
        sB[tid] = bhh[g * HID + c * 4 + q];
    }
    {
        float4 z = make_float4(0.f, 0.f, 0.f, 0.f);
        *(float4*)(&g_h[0][(c * 256 + tid) * 4]) = z;
    }

    unsigned base = g_bar_gen;
    gridbar(base + 1);

    const int b_g = tid & 7;           // 8 b-groups (8 rows each)
    const int q   = (tid >> 3) & 3;    // hidden col within CTA
    const int ks  = tid >> 5;          // 8-way k split (== warp id)
    const int q2  = tid & 3;
    const int bl2 = tid >> 2;
    const int k0  = ks * 64;

    const float* wr = Ws + (0 * 4 + q) * WS_STRIDE;
    const float* wz = Ws + (1 * 4 + q) * WS_STRIDE;
    const float* wn = Ws + (2 * 4 + q) * WS_STRIDE;

    for (int s = 0; s < STEPS; ++s) {
        const float* hin = g_h[s & 1];
        float* hout = g_h[(s + 1) & 1];

        for (int bt = 0; bt < 4; ++bt) {
            for (int i = tid; i < 64 * 128; i += 256) {
                int row = i >> 7, col = i & 127;
                float4 v = __ldcg((const float4*)(hin + (size_t)(bt * 64 + row) * HID + col * 4));
                *(float4*)(Hs + row * HS_STRIDE + col * 4) = v;
            }
            __syncthreads();

            unsigned long long ar2[8], az2[8], an2[8];
            #pragma unroll
            for (int j = 0; j < 8; ++j) { ar2[j] = 0ull; az2[j] = 0ull; an2[j] = 0ull; }

            const float* hb[8];
            #pragma unroll
            for (int j = 0; j < 8; ++j) hb[j] = Hs + (b_g + 8 * j) * HS_STRIDE;

            #pragma unroll 4
            for (int k = k0; k < k0 + 64; k += 4) {
                ulonglong2 w2r = *(const ulonglong2*)(wr + k);
                ulonglong2 w2z = *(const ulonglong2*)(wz + k);
                ulonglong2 w2n = *(const ulonglong2*)(wn + k);
                #pragma unroll
                for (int j = 0; j < 8; ++j) {
                    ulonglong2 h2 = *(const ulonglong2*)(hb[j] + k);
                    ar2[j] = fma2(h2.x, w2r.x, ar2[j]);
                    ar2[j] = fma2(h2.y, w2r.y, ar2[j]);
                    az2[j] = fma2(h2.x, w2z.x, az2[j]);
                    az2[j] = fma2(h2.y, w2z.y, az2[j]);
                    an2[j] = fma2(h2.x, w2n.x, an2[j]);
                    an2[j] = fma2(h2.y, w2n.y, an2[j]);
                }
            }

            #pragma unroll
            for (int j = 0; j < 8; ++j) {
                int b_l = b_g + 8 * j;
                float* p = part + (ks * 64 + b_l) * 12;
                float2 fr = *(float2*)(&ar2[j]);
                float2 fz = *(float2*)(&az2[j]);
                float2 fn = *(float2*)(&an2[j]);
                p[0 + q] = fr.x + fr.y;
                p[4 + q] = fz.x + fz.y;
                p[8 + q] = fn.x + fn.y;
            }
            __syncthreads();

            {
                float ar = 0.f, az = 0.f, an = 0.f;
                #pragma unroll
                for (int kq = 0; kq < 8; ++kq) {
                    const float* p = part + (kq * 64 + bl2) * 12;
                    ar += p[0 + q2];
                    az += p[4 + q2];
                    an += p[8 + q2];
                }
                int bglob = bt * 64 + bl2;
                size_t gib = ((size_t)s * BATCH + bglob) * GH + c * 4 + q2;
                float gr = __ldcg(g_gi + gib);
                float gz = __ldcg(g_gi + gib + HID);
                float gn = __ldcg(g_gi + gib + 2 * HID);
                float rg = 1.f / (1.f + expf(-(gr + ar + sB[0 + q2])));
                float zg = 1.f / (1.f + expf(-(gz + az + sB[4 + q2])));
                float ng = tanhf(gn + rg * (an + sB[8 + q2]));
                float hold = Hs[bl2 * HS_STRIDE + c * 4 + q2];
                float hnew = (1.f - zg) * ng + zg * hold;
                hout[(size_t)bglob * HID + c * 4 + q2] = hnew;
                if (s == STEPS - 1)
                    out[(size_t)bglob * HID + c * 4 + q2] = hnew;
            }
            __syncthreads();
        }
        gridbar(base + 2 + s);
    }
}

// ---------------- launcher ----------------
extern "C" void kernel_launch(void* const* d_in, const int* in_sizes, int n_in,
                              void* d_out, int out_size) {
    const float* x   = (const float*)d_in[0];
    const float* wih = (const float*)d_in[1];
    const float* whh = (const float*)d_in[2];
    const float* bih = (const float*)d_in[3];
    const float* bhh = (const float*)d_in[4];
    float* out = (float*)d_out;

    cudaFuncSetAttribute(k_gru_recur, cudaFuncAttributeMaxDynamicSharedMemorySize,
                         REC_SMEM_BYTES);
    cudaFuncSetAttribute(k_gemm_gi, cudaFuncAttributeMaxDynamicSharedMemorySize,
                         GEMM_SMEM);

    k_w_convert<<<(GH * ISZ) / 1024, 256>>>(wih);
    k_x_transpose<<<dim3(STEPS / 32, ISZ / 32, BATCH), dim3(32, 8)>>>(x);
    k_gemm_gi<<<dim3(GH / 128, MROWS / 128), 256, GEMM_SMEM>>>(bih);
    k_gru_recur<<<NCTA, 256, REC_SMEM_BYTES>>>(whh, bhh, out);
}

// round 4
// speedup vs baseline: 1.8620x; 1.5046x over previous
#include <cuda_runtime.h>
#include <cuda_bf16.h>
#include <cstdint>

#define BATCH 256
#define ISZ   512
#define STEPS 256
#define HID   512
#define GH    1536
#define NCTA  128
#define MROWS (STEPS * BATCH)     // 65536

// ---------------- scratch ----------------
__device__ __nv_bfloat16 g_xhi[(size_t)MROWS * ISZ];
__device__ __nv_bfloat16 g_xlo[(size_t)MROWS * ISZ];
__device__ __nv_bfloat16 g_whi[(size_t)GH * ISZ];
__device__ __nv_bfloat16 g_wlo[(size_t)GH * ISZ];
__device__ float g_gi[(size_t)MROWS * GH];
__device__ float g_h[2][BATCH * HID];
__device__ unsigned g_bar_cnt;
__device__ volatile unsigned g_bar_gen;

// ---------------- helpers ----------------
__device__ __forceinline__ uint32_t smem_to_u32(const void* p) {
    uint32_t a;
    asm("{ .reg .u64 t; cvta.to.shared.u64 t, %1; cvt.u32.u64 %0, t; }" : "=r"(a) : "l"(p));
    return a;
}
__device__ __forceinline__ void cp16(uint32_t dst, const void* src) {
    asm volatile("cp.async.cg.shared.global [%0], [%1], 16;" :: "r"(dst), "l"(src));
}
#define CP_COMMIT() asm volatile("cp.async.commit_group;" ::: "memory")
#define CP_WAIT(n)  asm volatile("cp.async.wait_group %0;" :: "n"(n) : "memory")

__device__ __forceinline__ void ldsm_x4(uint32_t addr, uint32_t r[4]) {
    asm volatile("ldmatrix.sync.aligned.m8n8.x4.shared.b16 {%0,%1,%2,%3}, [%4];"
                 : "=r"(r[0]), "=r"(r[1]), "=r"(r[2]), "=r"(r[3]) : "r"(addr));
}
__device__ __forceinline__ void mma_bf16(float d[4], const uint32_t a[4], const uint32_t b[2]) {
    asm volatile("mma.sync.aligned.m16n8k16.row.col.f32.bf16.bf16.f32 "
                 "{%0,%1,%2,%3}, {%4,%5,%6,%7}, {%8,%9}, {%0,%1,%2,%3};"
                 : "+f"(d[0]), "+f"(d[1]), "+f"(d[2]), "+f"(d[3])
                 : "r"(a[0]), "r"(a[1]), "r"(a[2]), "r"(a[3]), "r"(b[0]), "r"(b[1]));
}
__device__ __forceinline__ unsigned long long fma2(unsigned long long a,
                                                   unsigned long long b,
                                                   unsigned long long c) {
    unsigned long long d;
    asm("fma.rn.f32x2 %0, %1, %2, %3;" : "=l"(d) : "l"(a), "l"(b), "l"(c));
    return d;
}
__device__ __forceinline__ void split_bf16(float v, __nv_bfloat16& hi, __nv_bfloat16& lo) {
    hi = __float2bfloat16_rn(v);
    lo = __float2bfloat16_rn(v - __bfloat162float(hi));
}

// ---------------- Wih -> bf16 hi/lo ----------------
__global__ void k_w_convert(const float* __restrict__ wih) {
    size_t i = (size_t)blockIdx.x * 1024 + threadIdx.x * 4;
    #pragma unroll
    for (int j = 0; j < 4; ++j) {
        float v = wih[i + j];
        split_bf16(v, g_whi[i + j], g_wlo[i + j]);
    }
}

// ---------------- x [B][I][S] -> g_xhi/g_xlo [(s*B+b)][i] bf16 ----------------
__global__ void k_x_transpose(const float* __restrict__ x) {
    __shared__ float tile[32][33];
    int s0 = blockIdx.x * 32;
    int i0 = blockIdx.y * 32;
    int b  = blockIdx.z;
    int tx = threadIdx.x, ty = threadIdx.y;
    #pragma unroll
    for (int j = 0; j < 4; ++j)
        tile[ty + 8 * j][tx] = x[((size_t)b * ISZ + i0 + ty + 8 * j) * STEPS + s0 + tx];
    __syncthreads();
    #pragma unroll
    for (int j = 0; j < 4; ++j) {
        int s = s0 + ty + 8 * j;
        float v = tile[tx][ty + 8 * j];
        size_t o = ((size_t)s * BATCH + b) * ISZ + i0 + tx;
        split_bf16(v, g_xhi[o], g_xlo[o]);
    }
}

// ---------------- HMMA GEMM: gi = x_split @ Wih_split^T + bias_ih ----------------
#define SA 72
#define ATILE_B (128 * SA * 2)
#define GEMM_SMEM (2 * 4 * ATILE_B)

__device__ __forceinline__ void gi_issue_load(uint32_t sb, int tid, int m0, int n0,
                                              int chunk, int buf) {
    const int k0 = chunk * 64;
    const __nv_bfloat16* srcs[4] = {g_xhi, g_xlo, g_whi, g_wlo};
    const int rowbase[4] = {m0, m0, n0, n0};
    #pragma unroll
    for (int t = 0; t < 4; ++t) {
        const __nv_bfloat16* src = srcs[t];
        uint32_t dst0 = sb + buf * 4 * ATILE_B + t * ATILE_B;
        #pragma unroll
        for (int i = 0; i < 4; ++i) {
            int lin = tid + 256 * i;
            int row = lin >> 3;
            int cq  = lin & 7;
            cp16(dst0 + row * (SA * 2) + cq * 16,
                 src + (size_t)(rowbase[t] + row) * ISZ + k0 + cq * 8);
        }
    }
}

__global__ void __launch_bounds__(256, 1) k_gemm_gi(const float* __restrict__ bias_ih) {
    extern __shared__ char smem[];
    uint32_t sb = smem_to_u32(smem);
    const int tid = threadIdx.x;
    const int lane = tid & 31;
    const int wid = tid >> 5;
    const int wm = wid & 3;
    const int wn = wid >> 2;
    const int m0 = blockIdx.y * 128;
    const int n0 = blockIdx.x * 128;

    const int t4 = lane >> 3;
    const int arow = (t4 & 1) * 8 + (lane & 7);
    const int acol = (t4 >> 1) * 8;
    const int brow = (t4 >> 1) * 8 + (lane & 7);
    const int bcol = (t4 & 1) * 8;

    float acc[2][8][4];
    #pragma unroll
    for (int i = 0; i < 2; ++i)
        #pragma unroll
        for (int j = 0; j < 8; ++j)
            #pragma unroll
            for (int v = 0; v < 4; ++v) acc[i][j][v] = 0.f;

    gi_issue_load(sb, tid, m0, n0, 0, 0);
    CP_COMMIT();

    for (int c = 0; c < 8; ++c) {
        if (c < 7) {
            gi_issue_load(sb, tid, m0, n0, c + 1, (c + 1) & 1);
            CP_COMMIT();
            CP_WAIT(1);
        } else {
            CP_WAIT(0);
        }
        __syncthreads();
        const int buf = c & 1;
        const uint32_t bufb = sb + buf * 4 * ATILE_B;

        #pragma unroll
        for (int kk = 0; kk < 64; kk += 16) {
            uint32_t Ah[2][4], Al[2][4], Bh[8][2], Bl[8][2];
            #pragma unroll
            for (int mt = 0; mt < 2; ++mt) {
                uint32_t r = (wm * 32 + mt * 16 + arow) * (SA * 2) + (kk + acol) * 2;
                ldsm_x4(bufb + 0 * ATILE_B + r, Ah[mt]);
                ldsm_x4(bufb + 1 * ATILE_B + r, Al[mt]);
            }
            #pragma unroll
            for (int pt = 0; pt < 4; ++pt) {
                uint32_t r = (wn * 64 + pt * 16 + brow) * (SA * 2) + (kk + bcol) * 2;
                uint32_t q[4];
                ldsm_x4(bufb + 2 * ATILE_B + r, q);
                Bh[2 * pt][0] = q[0]; Bh[2 * pt][1] = q[1];
                Bh[2 * pt + 1][0] = q[2]; Bh[2 * pt + 1][1] = q[3];
                ldsm_x4(bufb + 3 * ATILE_B + r, q);
                Bl[2 * pt][0] = q[0]; Bl[2 * pt][1] = q[1];
                Bl[2 * pt + 1][0] = q[2]; Bl[2 * pt + 1][1] = q[3];
            }
            #pragma unroll
            for (int mt = 0; mt < 2; ++mt)
                #pragma unroll
                for (int nt = 0; nt < 8; ++nt) {
                    mma_bf16(acc[mt][nt], Ah[mt], Bh[nt]);
                    mma_bf16(acc[mt][nt], Ah[mt], Bl[nt]);
                    mma_bf16(acc[mt][nt], Al[mt], Bh[nt]);
                }
        }
        __syncthreads();
    }

    #pragma unroll
    for (int nt = 0; nt < 8; ++nt) {
        int n_base = n0 + wn * 64 + nt * 8 + (lane & 3) * 2;
        float2 bb = *(const float2*)(bias_ih + n_base);
        #pragma unroll
        for (int mt = 0; mt < 2; ++mt) {
            int m_base = m0 + wm * 32 + mt * 16 + (lane >> 2);
            float2 v0, v1;
            v0.x = acc[mt][nt][0] + bb.x;
            v0.y = acc[mt][nt][1] + bb.y;
            v1.x = acc[mt][nt][2] + bb.x;
            v1.y = acc[mt][nt][3] + bb.y;
            *(float2*)(g_gi + (size_t)m_base * GH + n_base) = v0;
            *(float2*)(g_gi + (size_t)(m_base + 8) * GH + n_base) = v1;
        }
    }
}

// ---------------- persistent GRU recurrence v2 ----------------
// 128 CTAs = 4 batch-groups (64 rows) x 32 col-groups (16 cols).
// Whh slice (48 rows x 512) resident fp32 in smem for the whole kernel.
// Thread owns 4 batches x 1 column x 3 gates -> fully local gate math.
__device__ __forceinline__ void gridbar(unsigned target) {
    __syncthreads();
    if (threadIdx.x == 0) {
        __threadfence();
        unsigned a = atomicAdd(&g_bar_cnt, 1u);
        if (a == NCTA - 1) {
            atomicExch(&g_bar_cnt, 0u);
            __threadfence();
            g_bar_gen = target;
        } else {
            while ((int)(g_bar_gen - target) < 0) __nanosleep(64);
        }
        __threadfence();
    }
    __syncthreads();
}

#define KW 516
#define REC_SMEM_BYTES ((48 * KW + 64 * KW) * 4)   // 231168 B

__device__ __forceinline__ float sigmoidf_(float v) { return 1.f / (1.f + expf(-v)); }

__global__ void __launch_bounds__(256, 1) k_gru_recur(
    const float* __restrict__ whh, const float* __restrict__ bhh,
    float* __restrict__ out)
{
    extern __shared__ float sm[];
    float* Ws = sm;                 // [col*3+g][KW]
    float* Hs = sm + 48 * KW;       // [b_local][KW]
    uint32_t hs_u32 = smem_to_u32(Hs);

    const int cta = blockIdx.x;
    const int cg  = cta & 31;       // col-group
    const int bg0 = cta >> 5;       // batch-group (0..3), 64 rows
    const int tid = threadIdx.x;
    const int bl  = tid & 15;       // batch lane (4 batches: bl+16j)
    const int col = tid >> 4;       // 0..15 local column
    const int gcol = cg * 16 + col;

    // resident Whh slice: Ws[(c*3+g)][k]
    for (int idx = tid; idx < 48 * 128; idx += 256) {
        int r = idx >> 7;           // 0..47
        int kq = idx & 127;
        int c = r / 3, g = r - c * 3;
        float4 v = *(const float4*)(whh + (size_t)(g * HID + cg * 16 + c) * HID + kq * 4);
        *(float4*)(Ws + r * KW + kq * 4) = v;
    }
    const float br = bhh[gcol];
    const float bz = bhh[HID + gcol];
    const float bn = bhh[2 * HID + gcol];

    {   // zero h buffer 0 (disjoint chunks)
        float4 z = make_float4(0.f, 0.f, 0.f, 0.f);
        *(float4*)(&g_h[0][(cta * 256 + tid) * 4]) = z;
    }

    unsigned base = g_bar_gen;
    gridbar(base + 1);

    const float* w0 = Ws + (col * 3 + 0) * KW;
    const float* w1 = Ws + (col * 3 + 1) * KW;
    const float* w2 = Ws + (col * 3 + 2) * KW;

    for (int s = 0; s < STEPS; ++s) {
        const float* hin = g_h[s & 1];
        float* hout = g_h[(s + 1) & 1];

        // prefetch gi for my 12 outputs
        float gr[4], gz[4], gn[4];
        #pragma unroll
        for (int j = 0; j < 4; ++j) {
            int bglob = bg0 * 64 + bl + 16 * j;
            size_t gib = ((size_t)s * BATCH + bglob) * GH + gcol;
            gr[j] = __ldcg(g_gi + gib);
            gz[j] = __ldcg(g_gi + gib + HID);
            gn[j] = __ldcg(g_gi + gib + 2 * HID);
        }

        // async h load: two k-halves (cols 0..255, 256..511)
        #pragma unroll
        for (int half = 0; half < 2; ++half) {
            #pragma unroll
            for (int it = 0; it < 16; ++it) {
                int lin = tid + 256 * it;        // 4096 float4 per half
                int row = lin >> 6;              // 0..63
                int cq  = (lin & 63) + half * 64;
                cp16(hs_u32 + (row * KW + cq * 4) * 4,
                     hin + (size_t)(bg0 * 64 + row) * HID + cq * 4);
            }
            CP_COMMIT();
        }

        unsigned long long a0[4], a1[4], a2[4];
        #pragma unroll
        for (int j = 0; j < 4; ++j) { a0[j] = 0ull; a1[j] = 0ull; a2[j] = 0ull; }

        CP_WAIT(1);
        __syncthreads();

        #pragma unroll 4
        for (int k = 0; k < 256; k += 4) {
            ulonglong2 v0 = *(const ulonglong2*)(w0 + k);
            ulonglong2 v1 = *(const ulonglong2*)(w1 + k);
            ulonglong2 v2 = *(const ulonglong2*)(w2 + k);
            #pragma unroll
            for (int j = 0; j < 4; ++j) {
                ulonglong2 h2 = *(const ulonglong2*)(Hs + (bl + 16 * j) * KW + k);
                a0[j] = fma2(h2.x, v0.x, a0[j]);
                a0[j] = fma2(h2.y, v0.y, a0[j]);
                a1[j] = fma2(h2.x, v1.x, a1[j]);
                a1[j] = fma2(h2.y, v1.y, a1[j]);
                a2[j] = fma2(h2.x, v2.x, a2[j]);
                a2[j] = fma2(h2.y, v2.y, a2[j]);
            }
        }

        CP_WAIT(0);
        __syncthreads();

        #pragma unroll 4
        for (int k = 256; k < 512; k += 4) {
            ulonglong2 v0 = *(const ulonglong2*)(w0 + k);
            ulonglong2 v1 = *(const ulonglong2*)(w1 + k);
            ulonglong2 v2 = *(const ulonglong2*)(w2 + k);
            #pragma unroll
            for (int j = 0; j < 4; ++j) {
                ulonglong2 h2 = *(const ulonglong2*)(Hs + (bl + 16 * j) * KW + k);
                a0[j] = fma2(h2.x, v0.x, a0[j]);
                a0[j] = fma2(h2.y, v0.y, a0[j]);
                a1[j] = fma2(h2.x, v1.x, a1[j]);
                a1[j] = fma2(h2.y, v1.y, a1[j]);
                a2[j] = fma2(h2.x, v2.x, a2[j]);
                a2[j] = fma2(h2.y, v2.y, a2[j]);
            }
        }

        // gates (fully local)
        #pragma unroll
        for (int j = 0; j < 4; ++j) {
            int b_l = bl + 16 * j;
            int bglob = bg0 * 64 + b_l;
            float2 f0 = *(float2*)(&a0[j]);
            float2 f1 = *(float2*)(&a1[j]);
            float2 f2 = *(float2*)(&a2[j]);
            float ar = f0.x + f0.y;
            float az = f1.x + f1.y;
            float an = f2.x + f2.y;
            float rg = sigmoidf_(gr[j] + ar + br);
            float zg = sigmoidf_(gz[j] + az + bz);
            float ng = tanhf(gn[j] + rg * (an + bn));
            float hold = Hs[b_l * KW + gcol];
            float hnew = (1.f - zg) * ng + zg * hold;
            hout[(size_t)bglob * HID + gcol] = hnew;
            if (s == STEPS - 1)
                out[(size_t)bglob * HID + gcol] = hnew;
        }

        gridbar(base + 2 + s);
    }
}

// ---------------- launcher ----------------
extern "C" void kernel_launch(void* const* d_in, const int* in_sizes, int n_in,
                              void* d_out, int out_size) {
    const float* x   = (const float*)d_in[0];
    const float* wih = (const float*)d_in[1];
    const float* whh = (const float*)d_in[2];
    const float* bih = (const float*)d_in[3];
    const float* bhh = (const float*)d_in[4];
    float* out = (float*)d_out;

    cudaFuncSetAttribute(k_gru_recur, cudaFuncAttributeMaxDynamicSharedMemorySize,
                         REC_SMEM_BYTES);
    cudaFuncSetAttribute(k_gemm_gi, cudaFuncAttributeMaxDynamicSharedMemorySize,
                         GEMM_SMEM);

    k_w_convert<<<(GH * ISZ) / 1024, 256>>>(wih);
    k_x_transpose<<<dim3(STEPS / 32, ISZ / 32, BATCH), dim3(32, 8)>>>(x);
    k_gemm_gi<<<dim3(GH / 128, MROWS / 128), 256, GEMM_SMEM>>>(bih);
    k_gru_recur<<<NCTA, 256, REC_SMEM_BYTES>>>(whh, bhh, out);
}

// round 5
// speedup vs baseline: 3.6769x; 1.9747x over previous
#include <cuda_runtime.h>
#include <cuda_bf16.h>
#include <cstdint>

#define BATCH 256
#define ISZ   512
#define STEPS 256
#define HID   512
#define GH    1536
#define NCTA  128
#define MROWS (STEPS * BATCH)     // 65536

// ---------------- scratch ----------------
__device__ __nv_bfloat16 g_xhi[(size_t)MROWS * ISZ];
__device__ __nv_bfloat16 g_xlo[(size_t)MROWS * ISZ];
__device__ __nv_bfloat16 g_whi[(size_t)GH * ISZ];
__device__ __nv_bfloat16 g_wlo[(size_t)GH * ISZ];
__device__ float g_gi[(size_t)MROWS * GH];
__device__ __nv_bfloat16 g_hbf[2][2][BATCH * HID];   // [ping][hi/lo]
__device__ unsigned g_bar_cnt;
__device__ volatile unsigned g_bar_gen;

// ---------------- helpers ----------------
__device__ __forceinline__ uint32_t smem_to_u32(const void* p) {
    uint32_t a;
    asm("{ .reg .u64 t; cvta.to.shared.u64 t, %1; cvt.u32.u64 %0, t; }" : "=r"(a) : "l"(p));
    return a;
}
__device__ __forceinline__ void cp16(uint32_t dst, const void* src) {
    asm volatile("cp.async.cg.shared.global [%0], [%1], 16;" :: "r"(dst), "l"(src));
}
#define CP_COMMIT() asm volatile("cp.async.commit_group;" ::: "memory")
#define CP_WAIT(n)  asm volatile("cp.async.wait_group %0;" :: "n"(n) : "memory")

__device__ __forceinline__ void ldsm_x4(uint32_t addr, uint32_t r[4]) {
    asm volatile("ldmatrix.sync.aligned.m8n8.x4.shared.b16 {%0,%1,%2,%3}, [%4];"
                 : "=r"(r[0]), "=r"(r[1]), "=r"(r[2]), "=r"(r[3]) : "r"(addr));
}
__device__ __forceinline__ void ldsm_x2(uint32_t addr, uint32_t r[2]) {
    asm volatile("ldmatrix.sync.aligned.m8n8.x2.shared.b16 {%0,%1}, [%2];"
                 : "=r"(r[0]), "=r"(r[1]) : "r"(addr));
}
__device__ __forceinline__ void mma_bf16(float d[4], const uint32_t a[4], const uint32_t b[2]) {
    asm volatile("mma.sync.aligned.m16n8k16.row.col.f32.bf16.bf16.f32 "
                 "{%0,%1,%2,%3}, {%4,%5,%6,%7}, {%8,%9}, {%0,%1,%2,%3};"
                 : "+f"(d[0]), "+f"(d[1]), "+f"(d[2]), "+f"(d[3])
                 : "r"(a[0]), "r"(a[1]), "r"(a[2]), "r"(a[3]), "r"(b[0]), "r"(b[1]));
}
__device__ __forceinline__ void split_bf16(float v, __nv_bfloat16& hi, __nv_bfloat16& lo) {
    hi = __float2bfloat16_rn(v);
    lo = __float2bfloat16_rn(v - __bfloat162float(hi));
}
__device__ __forceinline__ float sigmoidf_(float v) { return 1.f / (1.f + expf(-v)); }

// ---------------- Wih -> bf16 hi/lo ----------------
__global__ void k_w_convert(const float* __restrict__ wih) {
    size_t i = (size_t)blockIdx.x * 1024 + threadIdx.x * 4;
    #pragma unroll
    for (int j = 0; j < 4; ++j) {
        float v = wih[i + j];
        split_bf16(v, g_whi[i + j], g_wlo[i + j]);
    }
}

// ---------------- x [B][I][S] -> g_xhi/g_xlo [(s*B+b)][i] bf16 ----------------
__global__ void k_x_transpose(const float* __restrict__ x) {
    __shared__ float tile[32][33];
    int s0 = blockIdx.x * 32;
    int i0 = blockIdx.y * 32;
    int b  = blockIdx.z;
    int tx = threadIdx.x, ty = threadIdx.y;
    #pragma unroll
    for (int j = 0; j < 4; ++j)
        tile[ty + 8 * j][tx] = x[((size_t)b * ISZ + i0 + ty + 8 * j) * STEPS + s0 + tx];
    __syncthreads();
    #pragma unroll
    for (int j = 0; j < 4; ++j) {
        int s = s0 + ty + 8 * j;
        float v = tile[tx][ty + 8 * j];
        size_t o = ((size_t)s * BATCH + b) * ISZ + i0 + tx;
        split_bf16(v, g_xhi[o], g_xlo[o]);
    }
}

// ---------------- HMMA GEMM: gi = x_split @ Wih_split^T + bias_ih ----------------
#define SA 72
#define ATILE_B (128 * SA * 2)
#define GEMM_SMEM (2 * 4 * ATILE_B)

__device__ __forceinline__ void gi_issue_load(uint32_t sb, int tid, int m0, int n0,
                                              int chunk, int buf) {
    const int k0 = chunk * 64;
    const __nv_bfloat16* srcs[4] = {g_xhi, g_xlo, g_whi, g_wlo};
    const int rowbase[4] = {m0, m0, n0, n0};
    #pragma unroll
    for (int t = 0; t < 4; ++t) {
        const __nv_bfloat16* src = srcs[t];
        uint32_t dst0 = sb + buf * 4 * ATILE_B + t * ATILE_B;
        #pragma unroll
        for (int i = 0; i < 4; ++i) {
            int lin = tid + 256 * i;
            int row = lin >> 3;
            int cq  = lin & 7;
            cp16(dst0 + row * (SA * 2) + cq * 16,
                 src + (size_t)(rowbase[t] + row) * ISZ + k0 + cq * 8);
        }
    }
}

__global__ void __launch_bounds__(256, 1) k_gemm_gi(const float* __restrict__ bias_ih) {
    extern __shared__ char smem[];
    uint32_t sb = smem_to_u32(smem);
    const int tid = threadIdx.x;
    const int lane = tid & 31;
    const int wid = tid >> 5;
    const int wm = wid & 3;
    const int wn = wid >> 2;
    const int m0 = blockIdx.y * 128;
    const int n0 = blockIdx.x * 128;

    const int t4 = lane >> 3;
    const int arow = (t4 & 1) * 8 + (lane & 7);
    const int acol = (t4 >> 1) * 8;
    const int brow = (t4 >> 1) * 8 + (lane & 7);
    const int bcol = (t4 & 1) * 8;

    float acc[2][8][4];
    #pragma unroll
    for (int i = 0; i < 2; ++i)
        #pragma unroll
        for (int j = 0; j < 8; ++j)
            #pragma unroll
            for (int v = 0; v < 4; ++v) acc[i][j][v] = 0.f;

    gi_issue_load(sb, tid, m0, n0, 0, 0);
    CP_COMMIT();

    for (int c = 0; c < 8; ++c) {
        if (c < 7) {
            gi_issue_load(sb, tid, m0, n0, c + 1, (c + 1) & 1);
            CP_COMMIT();
            CP_WAIT(1);
        } else {
            CP_WAIT(0);
        }
        __syncthreads();
        const int buf = c & 1;
        const uint32_t bufb = sb + buf * 4 * ATILE_B;

        #pragma unroll
        for (int kk = 0; kk < 64; kk += 16) {
            uint32_t Ah[2][4], Al[2][4], Bh[8][2], Bl[8][2];
            #pragma unroll
            for (int mt = 0; mt < 2; ++mt) {
                uint32_t r = (wm * 32 + mt * 16 + arow) * (SA * 2) + (kk + acol) * 2;
                ldsm_x4(bufb + 0 * ATILE_B + r, Ah[mt]);
                ldsm_x4(bufb + 1 * ATILE_B + r, Al[mt]);
            }
            #pragma unroll
            for (int pt = 0; pt < 4; ++pt) {
                uint32_t r = (wn * 64 + pt * 16 + brow) * (SA * 2) + (kk + bcol) * 2;
                uint32_t q[4];
                ldsm_x4(bufb + 2 * ATILE_B + r, q);
                Bh[2 * pt][0] = q[0]; Bh[2 * pt][1] = q[1];
                Bh[2 * pt + 1][0] = q[2]; Bh[2 * pt + 1][1] = q[3];
                ldsm_x4(bufb + 3 * ATILE_B + r, q);
                Bl[2 * pt][0] = q[0]; Bl[2 * pt][1] = q[1];
                Bl[2 * pt + 1][0] = q[2]; Bl[2 * pt + 1][1] = q[3];
            }
            #pragma unroll
            for (int mt = 0; mt < 2; ++mt)
                #pragma unroll
                for (int nt = 0; nt < 8; ++nt) {
                    mma_bf16(acc[mt][nt], Ah[mt], Bh[nt]);
                    mma_bf16(acc[mt][nt], Ah[mt], Bl[nt]);
                    mma_bf16(acc[mt][nt], Al[mt], Bh[nt]);
                }
        }
        __syncthreads();
    }

    #pragma unroll
    for (int nt = 0; nt < 8; ++nt) {
        int n_base = n0 + wn * 64 + nt * 8 + (lane & 3) * 2;
        float2 bb = *(const float2*)(bias_ih + n_base);
        #pragma unroll
        for (int mt = 0; mt < 2; ++mt) {
            int m_base = m0 + wm * 32 + mt * 16 + (lane >> 2);
            float2 v0, v1;
            v0.x = acc[mt][nt][0] + bb.x;
            v0.y = acc[mt][nt][1] + bb.y;
            v1.x = acc[mt][nt][2] + bb.x;
            v1.y = acc[mt][nt][3] + bb.y;
            *(float2*)(g_gi + (size_t)m_base * GH + n_base) = v0;
            *(float2*)(g_gi + (size_t)(m_base + 8) * GH + n_base) = v1;
        }
    }
}

// ---------------- persistent GRU recurrence v3: HMMA ----------------
// 128 CTAs = 4 batch-groups (64 rows) x 32 col-groups (16 cols x 3 gates = 48 N-rows).
// B = Whh slice bf16 hi/lo resident in smem; A = h tile bf16 hi/lo streamed per step.
// 3-MMA hi/lo split. h_old kept in registers (same CTA produces & consumes it).
__device__ __forceinline__ void gridbar(unsigned target) {
    __syncthreads();
    if (threadIdx.x == 0) {
        __threadfence();
        unsigned a = atomicAdd(&g_bar_cnt, 1u);
        if (a == NCTA - 1) {
            atomicExch(&g_bar_cnt, 0u);
            __threadfence();
            g_bar_gen = target;
        } else {
            while ((int)(g_bar_gen - target) < 0) __nanosleep(64);
        }
        __threadfence();
    }
    __syncthreads();
}

#define A_HI 0
#define A_LO 65536                       // 64 rows x 1024 B
#define B_HI 131072
#define BSTR 520                         // bf16 per B row (1040 B, 4-bank shift/row)
#define B_LO (B_HI + 48 * BSTR * 2)      // 180992
#define REC2_SMEM (B_LO + 48 * BSTR * 2) // 230912
#define GH_STR 50                        // gh smem stride (floats)

// swizzled A offset: row-major 1024B rows, 16B units XORed with row&7
__device__ __forceinline__ uint32_t a_off(int row, int kb) {
    uint32_t u = ((uint32_t)kb >> 3) ^ (row & 7);
    return (uint32_t)row * 1024 + u * 16;
}

__global__ void __launch_bounds__(256, 1) k_gru_recur(
    const float* __restrict__ whh, const float* __restrict__ bhh,
    float* __restrict__ out)
{
    extern __shared__ char smem[];
    uint32_t sb = smem_to_u32(smem);
    float* gh = (float*)smem;                    // reuses A region post-MMA

    const int cta = blockIdx.x;
    const int cg  = cta & 31;       // col-group (16 cols)
    const int bg0 = cta >> 5;       // batch-group (64 rows)
    const int tid = threadIdx.x;
    const int lane = tid & 31;
    const int wid = tid >> 5;
    const int wm = wid & 3;         // m16 tile
    const int wn = wid >> 2;        // n24 tile

    const int t4 = lane >> 3;
    const int arow = (t4 & 1) * 8 + (lane & 7);
    const int acol = (t4 >> 1) * 8;
    const int brow = (t4 >> 1) * 8 + (lane & 7);
    const int bcol = (t4 & 1) * 8;
    // x2 address (first 16 lanes matter; give all lanes valid addrs)
    const int brow2 = lane & 7;
    const int bcol2 = ((lane >> 3) & 1) * 8;

    // ---- load + convert resident Whh slice: B row n = g*16+c ----
    for (int idx = tid; idx < 48 * 128; idx += 256) {
        int r = idx >> 7;            // 0..47
        int kq = idx & 127;          // float4 index
        int g = r >> 4, c = r & 15;
        float4 v = *(const float4*)(whh + (size_t)(g * HID + cg * 16 + c) * HID + kq * 4);
        __nv_bfloat16 hi[4], lo[4];
        split_bf16(v.x, hi[0], lo[0]);
        split_bf16(v.y, hi[1], lo[1]);
        split_bf16(v.z, hi[2], lo[2]);
        split_bf16(v.w, hi[3], lo[3]);
        *(uint2*)(smem + B_HI + r * (BSTR * 2) + kq * 8) = *(uint2*)hi;
        *(uint2*)(smem + B_LO + r * (BSTR * 2) + kq * 8) = *(uint2*)lo;
    }

    // bias for gate phase: thread t -> b = t>>2, cols cq*4..cq*4+3
    const int gb = tid >> 2;         // local batch 0..63
    const int cq = tid & 3;
    const int c0 = cq * 4;
    const int gcol0 = cg * 16 + c0;
    float br[4], bz[4], bn[4];
    #pragma unroll
    for (int i = 0; i < 4; ++i) {
        br[i] = bhh[gcol0 + i];
        bz[i] = bhh[HID + gcol0 + i];
        bn[i] = bhh[2 * HID + gcol0 + i];
    }

    // zero h bf16 buffer 0 (hi+lo): 32768 chunks of 16B, disjoint per thread
    {
        uint4 z = make_uint4(0, 0, 0, 0);
        *(uint4*)((char*)g_hbf[0] + ((size_t)cta * 256 + tid) * 16) = z;
    }
    float h_old[4] = {0.f, 0.f, 0.f, 0.f};

    unsigned base = g_bar_gen;
    gridbar(base + 1);

    const uint32_t bhi = sb + B_HI;
    const uint32_t blo = sb + B_LO;
    const int nb = wn * 24;          // warp's N base

    for (int s = 0; s < STEPS; ++s) {
        const int cur = s & 1, nxt = cur ^ 1;
        const __nv_bfloat16* hsrc_hi = g_hbf[cur][0];
        const __nv_bfloat16* hsrc_lo = g_hbf[cur][1];

        // prefetch gi (3 gates x 4 cols, float4 each)
        const int bglob = bg0 * 64 + gb;
        const float* gip = g_gi + ((size_t)s * BATCH + bglob) * GH;
        float4 gr4 = __ldcg((const float4*)(gip + gcol0));
        float4 gz4 = __ldcg((const float4*)(gip + HID + gcol0));
        float4 gn4 = __ldcg((const float4*)(gip + 2 * HID + gcol0));

        // issue A chunks 0,1 (each: 64 rows x 128 k, hi+lo = 2048 cp16)
        #pragma unroll
        for (int pre = 0; pre < 2; ++pre) {
            #pragma unroll
            for (int i = 0; i < 8; ++i) {
                int lin = tid + 256 * i;            // 0..2047
                int half = lin >> 10;               // 0=hi 1=lo
                int r = lin & 1023;
                int row = r >> 4;
                int kb = pre * 128 + (r & 15) * 8;
                const __nv_bfloat16* src = half ? hsrc_lo : hsrc_hi;
                cp16(sb + (half ? A_LO : A_HI) + a_off(row, kb),
                     src + (size_t)(bg0 * 64 + row) * HID + kb);
            }
            CP_COMMIT();
        }

        float acc[3][4];
        #pragma unroll
        for (int j = 0; j < 3; ++j)
            #pragma unroll
            for (int v = 0; v < 4; ++v) acc[j][v] = 0.f;

        for (int kc = 0; kc < 4; ++kc) {
            if (kc < 3) CP_WAIT(1); else CP_WAIT(0);
            __syncthreads();
            if (kc < 2) {   // issue chunk kc+2
                int pre = kc + 2;
                #pragma unroll
                for (int i = 0; i < 8; ++i) {
                    int lin = tid + 256 * i;
                    int half = lin >> 10;
                    int r = lin & 1023;
                    int row = r >> 4;
                    int kb = pre * 128 + (r & 15) * 8;
                    const __nv_bfloat16* src = half ? hsrc_lo : hsrc_hi;
                    cp16(sb + (half ? A_LO : A_HI) + a_off(row, kb),
                         src + (size_t)(bg0 * 64 + row) * HID + kb);
                }
                CP_COMMIT();
            }
            #pragma unroll
            for (int t = 0; t < 8; ++t) {
                const int kk = kc * 128 + t * 16;
                uint32_t Ah[4], Al[4], Bh[3][2], Bl[3][2];
                {
                    int rr = wm * 16 + arow;
                    ldsm_x4(sb + A_HI + a_off(rr, kk + acol), Ah);
                    ldsm_x4(sb + A_LO + a_off(rr, kk + acol), Al);
                }
                {
                    uint32_t q[4];
                    uint32_t r16 = (nb + brow) * (BSTR * 2) + (kk + bcol) * 2;
                    ldsm_x4(bhi + r16, q);
                    Bh[0][0] = q[0]; Bh[0][1] = q[1];
                    Bh[1][0] = q[2]; Bh[1][1] = q[3];
                    ldsm_x4(blo + r16, q);
                    Bl[0][0] = q[0]; Bl[0][1] = q[1];
                    Bl[1][0] = q[2]; Bl[1][1] = q[3];
                    uint32_t r8 = (nb + 16 + brow2) * (BSTR * 2) + (kk + bcol2) * 2;
                    ldsm_x2(bhi + r8, Bh[2]);
                    ldsm_x2(blo + r8, Bl[2]);
                }
                #pragma unroll
                for (int nt = 0; nt < 3; ++nt) {
                    mma_bf16(acc[nt], Ah, Bh[nt]);
                    mma_bf16(acc[nt], Ah, Bl[nt]);
                    mma_bf16(acc[nt], Al, Bh[nt]);
                }
            }
        }
        __syncthreads();   // all MMAs done reading A -> safe to overwrite with gh

        // write gh fragments: [64][GH_STR]
        {
            int row0 = wm * 16 + (lane >> 2);
            int col0 = nb + (lane & 3) * 2;
            #pragma unroll
            for (int nt = 0; nt < 3; ++nt) {
                *(float2*)(gh + row0 * GH_STR + col0 + nt * 8) = make_float2(acc[nt][0], acc[nt][1]);
                *(float2*)(gh + (row0 + 8) * GH_STR + col0 + nt * 8) = make_float2(acc[nt][2], acc[nt][3]);
            }
        }
        __syncthreads();

        // gate phase: thread -> (b = gb, cols c0..c0+3); n index = g*16+c
        {
            float grv[4] = {gr4.x, gr4.y, gr4.z, gr4.w};
            float gzv[4] = {gz4.x, gz4.y, gz4.z, gz4.w};
            float gnv[4] = {gn4.x, gn4.y, gn4.z, gn4.w};
            __nv_bfloat16 hi4[4], lo4[4];
            float hnew4[4];
            #pragma unroll
            for (int i = 0; i < 4; ++i) {
                int c = c0 + i;
                float ar = gh[gb * GH_STR + 0 * 16 + c];
                float az = gh[gb * GH_STR + 1 * 16 + c];
                float an = gh[gb * GH_STR + 2 * 16 + c];
                float rg = sigmoidf_(grv[i] + ar + br[i]);
                float zg = sigmoidf_(gzv[i] + az + bz[i]);
                float ng = tanhf(gnv[i] + rg * (an + bn[i]));
                float hnew = (1.f - zg) * ng + zg * h_old[i];
                h_old[i] = hnew;
                hnew4[i] = hnew;
                split_bf16(hnew, hi4[i], lo4[i]);
            }
            size_t ho = (size_t)bglob * HID + gcol0;
            *(uint2*)(g_hbf[nxt][0] + ho) = *(uint2*)hi4;
            *(uint2*)(g_hbf[nxt][1] + ho) = *(uint2*)lo4;
            if (s == STEPS - 1)
                *(float4*)(out + ho) = *(float4*)hnew4;
        }

        gridbar(base + 2 + s);
    }
}

// ---------------- launcher ----------------
extern "C" void kernel_launch(void* const* d_in, const int* in_sizes, int n_in,
                              void* d_out, int out_size) {
    const float* x   = (const float*)d_in[0];
    const float* wih = (const float*)d_in[1];
    const float* whh = (const float*)d_in[2];
    const float* bih = (const float*)d_in[3];
    const float* bhh = (const float*)d_in[4];
    float* out = (float*)d_out;

    cudaFuncSetAttribute(k_gru_recur, cudaFuncAttributeMaxDynamicSharedMemorySize,
                         REC2_SMEM);
    cudaFuncSetAttribute(k_gemm_gi, cudaFuncAttributeMaxDynamicSharedMemorySize,
                         GEMM_SMEM);

    k_w_convert<<<(GH * ISZ) / 1024, 256>>>(wih);
    k_x_transpose<<<dim3(STEPS / 32, ISZ / 32, BATCH), dim3(32, 8)>>>(x);
    k_gemm_gi<<<dim3(GH / 128, MROWS / 128), 256, GEMM_SMEM>>>(bih);
    k_gru_recur<<<NCTA, 256, REC2_SMEM>>>(whh, bhh, out);
}

// round 6
// speedup vs baseline: 4.1111x; 1.1181x over previous
#include <cuda_runtime.h>
#include <cuda_bf16.h>
#include <cstdint>

#define BATCH 256
#define ISZ   512
#define STEPS 256
#define HID   512
#define GH    1536
#define NCTA  128
#define MROWS (STEPS * BATCH)     // 65536

// ---------------- scratch ----------------
__device__ __nv_bfloat16 g_xhi[(size_t)MROWS * ISZ];
__device__ __nv_bfloat16 g_xlo[(size_t)MROWS * ISZ];
__device__ __nv_bfloat16 g_whi[(size_t)GH * ISZ];
__device__ __nv_bfloat16 g_wlo[(size_t)GH * ISZ];
__device__ float g_gi[(size_t)MROWS * GH];
__device__ __nv_bfloat16 g_hbf[2][2][BATCH * HID];   // [ping][hi/lo]
__device__ unsigned g_bar_cnt;
__device__ volatile unsigned g_bar_gen;

// ---------------- helpers ----------------
__device__ __forceinline__ uint32_t smem_to_u32(const void* p) {
    uint32_t a;
    asm("{ .reg .u64 t; cvta.to.shared.u64 t, %1; cvt.u32.u64 %0, t; }" : "=r"(a) : "l"(p));
    return a;
}
__device__ __forceinline__ void cp16(uint32_t dst, const void* src) {
    asm volatile("cp.async.cg.shared.global [%0], [%1], 16;" :: "r"(dst), "l"(src));
}
#define CP_COMMIT() asm volatile("cp.async.commit_group;" ::: "memory")
#define CP_WAIT(n)  asm volatile("cp.async.wait_group %0;" :: "n"(n) : "memory")

__device__ __forceinline__ void ldsm_x4(uint32_t addr, uint32_t r[4]) {
    asm volatile("ldmatrix.sync.aligned.m8n8.x4.shared.b16 {%0,%1,%2,%3}, [%4];"
                 : "=r"(r[0]), "=r"(r[1]), "=r"(r[2]), "=r"(r[3]) : "r"(addr));
}
__device__ __forceinline__ void ldsm_x2(uint32_t addr, uint32_t r[2]) {
    asm volatile("ldmatrix.sync.aligned.m8n8.x2.shared.b16 {%0,%1}, [%2];"
                 : "=r"(r[0]), "=r"(r[1]) : "r"(addr));
}
__device__ __forceinline__ void mma_bf16(float d[4], const uint32_t a[4], const uint32_t b[2]) {
    asm volatile("mma.sync.aligned.m16n8k16.row.col.f32.bf16.bf16.f32 "
                 "{%0,%1,%2,%3}, {%4,%5,%6,%7}, {%8,%9}, {%0,%1,%2,%3};"
                 : "+f"(d[0]), "+f"(d[1]), "+f"(d[2]), "+f"(d[3])
                 : "r"(a[0]), "r"(a[1]), "r"(a[2]), "r"(a[3]), "r"(b[0]), "r"(b[1]));
}
__device__ __forceinline__ void split_bf16(float v, __nv_bfloat16& hi, __nv_bfloat16& lo) {
    hi = __float2bfloat16_rn(v);
    lo = __float2bfloat16_rn(v - __bfloat162float(hi));
}
__device__ __forceinline__ float fast_sigmoid(float v) {
    return __fdividef(1.f, 1.f + __expf(-v));
}
__device__ __forceinline__ float fast_tanh(float v) {
    float e = __expf(-2.f * v);
    return __fdividef(1.f - e, 1.f + e);
}

// ---------------- Wih -> bf16 hi/lo ----------------
__global__ void k_w_convert(const float* __restrict__ wih) {
    size_t i = (size_t)blockIdx.x * 1024 + threadIdx.x * 4;
    #pragma unroll
    for (int j = 0; j < 4; ++j) {
        float v = wih[i + j];
        split_bf16(v, g_whi[i + j], g_wlo[i + j]);
    }
}

// ---------------- x [B][I][S] -> g_xhi/g_xlo [(s*B+b)][i] bf16 ----------------
__global__ void k_x_transpose(const float* __restrict__ x) {
    __shared__ float tile[32][33];
    int s0 = blockIdx.x * 32;
    int i0 = blockIdx.y * 32;
    int b  = blockIdx.z;
    int tx = threadIdx.x, ty = threadIdx.y;
    #pragma unroll
    for (int j = 0; j < 4; ++j)
        tile[ty + 8 * j][tx] = x[((size_t)b * ISZ + i0 + ty + 8 * j) * STEPS + s0 + tx];
    __syncthreads();
    #pragma unroll
    for (int j = 0; j < 4; ++j) {
        int s = s0 + ty + 8 * j;
        float v = tile[tx][ty + 8 * j];
        size_t o = ((size_t)s * BATCH + b) * ISZ + i0 + tx;
        split_bf16(v, g_xhi[o], g_xlo[o]);
    }
}

// ---------------- HMMA GEMM: gi = x_split @ Wih_split^T + bias_ih ----------------
#define SA 72
#define ATILE_B (128 * SA * 2)
#define GEMM_SMEM (2 * 4 * ATILE_B)

__device__ __forceinline__ void gi_issue_load(uint32_t sb, int tid, int m0, int n0,
                                              int chunk, int buf) {
    const int k0 = chunk * 64;
    const __nv_bfloat16* srcs[4] = {g_xhi, g_xlo, g_whi, g_wlo};
    const int rowbase[4] = {m0, m0, n0, n0};
    #pragma unroll
    for (int t = 0; t < 4; ++t) {
        const __nv_bfloat16* src = srcs[t];
        uint32_t dst0 = sb + buf * 4 * ATILE_B + t * ATILE_B;
        #pragma unroll
        for (int i = 0; i < 4; ++i) {
            int lin = tid + 256 * i;
            int row = lin >> 3;
            int cq  = lin & 7;
            cp16(dst0 + row * (SA * 2) + cq * 16,
                 src + (size_t)(rowbase[t] + row) * ISZ + k0 + cq * 8);
        }
    }
}

__global__ void __launch_bounds__(256, 1) k_gemm_gi(const float* __restrict__ bias_ih) {
    extern __shared__ char smem[];
    uint32_t sb = smem_to_u32(smem);
    const int tid = threadIdx.x;
    const int lane = tid & 31;
    const int wid = tid >> 5;
    const int wm = wid & 3;
    const int wn = wid >> 2;
    const int m0 = blockIdx.y * 128;
    const int n0 = blockIdx.x * 128;

    const int t4 = lane >> 3;
    const int arow = (t4 & 1) * 8 + (lane & 7);
    const int acol = (t4 >> 1) * 8;
    const int brow = (t4 >> 1) * 8 + (lane & 7);
    const int bcol = (t4 & 1) * 8;

    float acc[2][8][4];
    #pragma unroll
    for (int i = 0; i < 2; ++i)
        #pragma unroll
        for (int j = 0; j < 8; ++j)
            #pragma unroll
            for (int v = 0; v < 4; ++v) acc[i][j][v] = 0.f;

    gi_issue_load(sb, tid, m0, n0, 0, 0);
    CP_COMMIT();

    for (int c = 0; c < 8; ++c) {
        if (c < 7) {
            gi_issue_load(sb, tid, m0, n0, c + 1, (c + 1) & 1);
            CP_COMMIT();
            CP_WAIT(1);
        } else {
            CP_WAIT(0);
        }
        __syncthreads();
        const int buf = c & 1;
        const uint32_t bufb = sb + buf * 4 * ATILE_B;

        #pragma unroll
        for (int kk = 0; kk < 64; kk += 16) {
            uint32_t Ah[2][4], Al[2][4], Bh[8][2], Bl[8][2];
            #pragma unroll
            for (int mt = 0; mt < 2; ++mt) {
                uint32_t r = (wm * 32 + mt * 16 + arow) * (SA * 2) + (kk + acol) * 2;
                ldsm_x4(bufb + 0 * ATILE_B + r, Ah[mt]);
                ldsm_x4(bufb + 1 * ATILE_B + r, Al[mt]);
            }
            #pragma unroll
            for (int pt = 0; pt < 4; ++pt) {
                uint32_t r = (wn * 64 + pt * 16 + brow) * (SA * 2) + (kk + bcol) * 2;
                uint32_t q[4];
                ldsm_x4(bufb + 2 * ATILE_B + r, q);
                Bh[2 * pt][0] = q[0]; Bh[2 * pt][1] = q[1];
                Bh[2 * pt + 1][0] = q[2]; Bh[2 * pt + 1][1] = q[3];
                ldsm_x4(bufb + 3 * ATILE_B + r, q);
                Bl[2 * pt][0] = q[0]; Bl[2 * pt][1] = q[1];
                Bl[2 * pt + 1][0] = q[2]; Bl[2 * pt + 1][1] = q[3];
            }
            #pragma unroll
            for (int mt = 0; mt < 2; ++mt)
                #pragma unroll
                for (int nt = 0; nt < 8; ++nt) {
                    mma_bf16(acc[mt][nt], Ah[mt], Bh[nt]);
                    mma_bf16(acc[mt][nt], Ah[mt], Bl[nt]);
                    mma_bf16(acc[mt][nt], Al[mt], Bh[nt]);
                }
        }
        __syncthreads();
    }

    #pragma unroll
    for (int nt = 0; nt < 8; ++nt) {
        int n_base = n0 + wn * 64 + nt * 8 + (lane & 3) * 2;
        float2 bb = *(const float2*)(bias_ih + n_base);
        #pragma unroll
        for (int mt = 0; mt < 2; ++mt) {
            int m_base = m0 + wm * 32 + mt * 16 + (lane >> 2);
            float2 v0, v1;
            v0.x = acc[mt][nt][0] + bb.x;
            v0.y = acc[mt][nt][1] + bb.y;
            v1.x = acc[mt][nt][2] + bb.x;
            v1.y = acc[mt][nt][3] + bb.y;
            *(float2*)(g_gi + (size_t)m_base * GH + n_base) = v0;
            *(float2*)(g_gi + (size_t)(m_base + 8) * GH + n_base) = v1;
        }
    }
}

// ---------------- persistent GRU recurrence v4: HMMA + deep prefetch ----------------
__device__ __forceinline__ void gridbar(unsigned target) {
    __syncthreads();
    if (threadIdx.x == 0) {
        __threadfence();
        unsigned a = atomicAdd(&g_bar_cnt, 1u);
        if (a == NCTA - 1) {
            atomicExch(&g_bar_cnt, 0u);
            __threadfence();
            g_bar_gen = target;
        } else {
            while ((int)(g_bar_gen - target) < 0) __nanosleep(32);
        }
        __threadfence();
    }
    __syncthreads();
}

#define A_HI 0
#define A_LO 65536
#define B_HI 131072
#define BSTR 520
#define B_LO (B_HI + 48 * BSTR * 2)
#define REC2_SMEM (B_LO + 48 * BSTR * 2)
#define GH_STR 50

__device__ __forceinline__ uint32_t a_off(int row, int kb) {
    uint32_t u = ((uint32_t)kb >> 3) ^ (row & 7);
    return (uint32_t)row * 1024 + u * 16;
}

__global__ void __launch_bounds__(256, 1) k_gru_recur(
    const float* __restrict__ whh, const float* __restrict__ bhh,
    float* __restrict__ out)
{
    extern __shared__ char smem[];
    uint32_t sb = smem_to_u32(smem);
    float* gh = (float*)smem;

    const int cta = blockIdx.x;
    const int cg  = cta & 31;
    const int bg0 = cta >> 5;
    const int tid = threadIdx.x;
    const int lane = tid & 31;
    const int wid = tid >> 5;
    const int wm = wid & 3;
    const int wn = wid >> 2;

    const int t4 = lane >> 3;
    const int arow = (t4 & 1) * 8 + (lane & 7);
    const int acol = (t4 >> 1) * 8;
    const int brow = (t4 >> 1) * 8 + (lane & 7);
    const int bcol = (t4 & 1) * 8;
    const int brow2 = lane & 7;
    const int bcol2 = ((lane >> 3) & 1) * 8;

    for (int idx = tid; idx < 48 * 128; idx += 256) {
        int r = idx >> 7;
        int kq = idx & 127;
        int g = r >> 4, c = r & 15;
        float4 v = *(const float4*)(whh + (size_t)(g * HID + cg * 16 + c) * HID + kq * 4);
        __nv_bfloat16 hi[4], lo[4];
        split_bf16(v.x, hi[0], lo[0]);
        split_bf16(v.y, hi[1], lo[1]);
        split_bf16(v.z, hi[2], lo[2]);
        split_bf16(v.w, hi[3], lo[3]);
        *(uint2*)(smem + B_HI + r * (BSTR * 2) + kq * 8) = *(uint2*)hi;
        *(uint2*)(smem + B_LO + r * (BSTR * 2) + kq * 8) = *(uint2*)lo;
    }

    const int gb = tid >> 2;
    const int cq = tid & 3;
    const int c0 = cq * 4;
    const int gcol0 = cg * 16 + c0;
    float br[4], bz[4], bn[4];
    #pragma unroll
    for (int i = 0; i < 4; ++i) {
        br[i] = bhh[gcol0 + i];
        bz[i] = bhh[HID + gcol0 + i];
        bn[i] = bhh[2 * HID + gcol0 + i];
    }

    {
        uint4 z = make_uint4(0, 0, 0, 0);
        *(uint4*)((char*)g_hbf[0] + ((size_t)cta * 256 + tid) * 16) = z;
    }
    float h_old[4] = {0.f, 0.f, 0.f, 0.f};

    unsigned base = g_bar_gen;
    gridbar(base + 1);

    const uint32_t bhi = sb + B_HI;
    const uint32_t blo = sb + B_LO;
    const int nb = wn * 24;
    const int bglob = bg0 * 64 + gb;

    for (int s = 0; s < STEPS; ++s) {
        const int cur = s & 1, nxt = cur ^ 1;
        const __nv_bfloat16* hsrc_hi = g_hbf[cur][0];
        const __nv_bfloat16* hsrc_lo = g_hbf[cur][1];

        // issue ALL 4 A chunks up front (deep pipeline; loads hide under MMA)
        #pragma unroll
        for (int pre = 0; pre < 4; ++pre) {
            #pragma unroll
            for (int i = 0; i < 8; ++i) {
                int lin = tid + 256 * i;
                int half = lin >> 10;
                int r = lin & 1023;
                int row = r >> 4;
                int kb = pre * 128 + (r & 15) * 8;
                const __nv_bfloat16* src = half ? hsrc_lo : hsrc_hi;
                cp16(sb + (half ? A_LO : A_HI) + a_off(row, kb),
                     src + (size_t)(bg0 * 64 + row) * HID + kb);
            }
            CP_COMMIT();
        }

        // gi prefetch (after the critical cp.async burst)
        const float* gip = g_gi + ((size_t)s * BATCH + bglob) * GH;
        float4 gr4 = __ldcg((const float4*)(gip + gcol0));
        float4 gz4 = __ldcg((const float4*)(gip + HID + gcol0));
        float4 gn4 = __ldcg((const float4*)(gip + 2 * HID + gcol0));

        float acc[3][4];
        #pragma unroll
        for (int j = 0; j < 3; ++j)
            #pragma unroll
            for (int v = 0; v < 4; ++v) acc[j][v] = 0.f;

        #pragma unroll
        for (int kc = 0; kc < 4; ++kc) {
            if (kc == 0)      CP_WAIT(3);
            else if (kc == 1) CP_WAIT(2);
            else if (kc == 2) CP_WAIT(1);
            else              CP_WAIT(0);
            __syncthreads();

            #pragma unroll
            for (int t = 0; t < 8; ++t) {
                const int kk = kc * 128 + t * 16;
                uint32_t Ah[4], Al[4], Bh[3][2], Bl[3][2];
                {
                    int rr = wm * 16 + arow;
                    ldsm_x4(sb + A_HI + a_off(rr, kk + acol), Ah);
                    ldsm_x4(sb + A_LO + a_off(rr, kk + acol), Al);
                }
                {
                    uint32_t q[4];
                    uint32_t r16 = (nb + brow) * (BSTR * 2) + (kk + bcol) * 2;
                    ldsm_x4(bhi + r16, q);
                    Bh[0][0] = q[0]; Bh[0][1] = q[1];
                    Bh[1][0] = q[2]; Bh[1][1] = q[3];
                    ldsm_x4(blo + r16, q);
                    Bl[0][0] = q[0]; Bl[0][1] = q[1];
                    Bl[1][0] = q[2]; Bl[1][1] = q[3];
                    uint32_t r8 = (nb + 16 + brow2) * (BSTR * 2) + (kk + bcol2) * 2;
                    ldsm_x2(bhi + r8, Bh[2]);
                    ldsm_x2(blo + r8, Bl[2]);
                }
                #pragma unroll
                for (int nt = 0; nt < 3; ++nt) {
                    mma_bf16(acc[nt], Ah, Bh[nt]);
                    mma_bf16(acc[nt], Ah, Bl[nt]);
                    mma_bf16(acc[nt], Al, Bh[nt]);
                }
            }
        }
        __syncthreads();   // A reads done -> safe to overwrite with gh

        {
            int row0 = wm * 16 + (lane >> 2);
            int col0 = nb + (lane & 3) * 2;
            #pragma unroll
            for (int nt = 0; nt < 3; ++nt) {
                *(float2*)(gh + row0 * GH_STR + col0 + nt * 8) = make_float2(acc[nt][0], acc[nt][1]);
                *(float2*)(gh + (row0 + 8) * GH_STR + col0 + nt * 8) = make_float2(acc[nt][2], acc[nt][3]);
            }
        }
        __syncthreads();

        {
            float grv[4] = {gr4.x, gr4.y, gr4.z, gr4.w};
            float gzv[4] = {gz4.x, gz4.y, gz4.z, gz4.w};
            float gnv[4] = {gn4.x, gn4.y, gn4.z, gn4.w};
            __nv_bfloat16 hi4[4], lo4[4];
            float hnew4[4];
            #pragma unroll
            for (int i = 0; i < 4; ++i) {
                int c = c0 + i;
                float ar = gh[gb * GH_STR + 0 * 16 + c];
                float az = gh[gb * GH_STR + 1 * 16 + c];
                float an = gh[gb * GH_STR + 2 * 16 + c];
                float rg = fast_sigmoid(grv[i] + ar + br[i]);
                float zg = fast_sigmoid(gzv[i] + az + bz[i]);
                float ng = fast_tanh(gnv[i] + rg * (an + bn[i]));
                float hnew = (1.f - zg) * ng + zg * h_old[i];
                h_old[i] = hnew;
                hnew4[i] = hnew;
                split_bf16(hnew, hi4[i], lo4[i]);
            }
            size_t ho = (size_t)bglob * HID + gcol0;
            *(uint2*)(g_hbf[nxt][0] + ho) = *(uint2*)hi4;
            *(uint2*)(g_hbf[nxt][1] + ho) = *(uint2*)lo4;
            if (s == STEPS - 1)
                *(float4*)(out + ho) = *(float4*)hnew4;
        }

        gridbar(base + 2 + s);
    }
}

// ---------------- launcher ----------------
extern "C" void kernel_launch(void* const* d_in, const int* in_sizes, int n_in,
                              void* d_out, int out_size) {
    const float* x   = (const float*)d_in[0];
    const float* wih = (const float*)d_in[1];
    const float* whh = (const float*)d_in[2];
    const float* bih = (const float*)d_in[3];
    const float* bhh = (const float*)d_in[4];
    float* out = (float*)d_out;

    cudaFuncSetAttribute(k_gru_recur, cudaFuncAttributeMaxDynamicSharedMemorySize,
                         REC2_SMEM);
    cudaFuncSetAttribute(k_gemm_gi, cudaFuncAttributeMaxDynamicSharedMemorySize,
                         GEMM_SMEM);

    k_w_convert<<<(GH * ISZ) / 1024, 256>>>(wih);
    k_x_transpose<<<dim3(STEPS / 32, ISZ / 32, BATCH), dim3(32, 8)>>>(x);
    k_gemm_gi<<<dim3(GH / 128, MROWS / 128), 256, GEMM_SMEM>>>(bih);
    k_gru_recur<<<NCTA, 256, REC2_SMEM>>>(whh, bhh, out);
}

// round 7
// speedup vs baseline: 4.2846x; 1.0422x over previous
#include <cuda_runtime.h>
#include <cuda_bf16.h>
#include <cstdint>

#define BATCH 256
#define ISZ   512
#define STEPS 256
#define HID   512
#define GH    1536
#define NCTA  128
#define MROWS (STEPS * BATCH)     // 65536

// ---------------- scratch ----------------
__device__ __nv_bfloat16 g_xhi[(size_t)MROWS * ISZ];
__device__ __nv_bfloat16 g_xlo[(size_t)MROWS * ISZ];
__device__ __nv_bfloat16 g_whi[(size_t)GH * ISZ];
__device__ __nv_bfloat16 g_wlo[(size_t)GH * ISZ];
__device__ float g_gi[(size_t)MROWS * GH];
__device__ __nv_bfloat16 g_hbf[2][2][BATCH * HID];   // [ping][hi/lo]
__device__ unsigned g_bg_cnt[4];
__device__ unsigned g_bg_gen[4];

// ---------------- helpers ----------------
__device__ __forceinline__ uint32_t smem_to_u32(const void* p) {
    uint32_t a;
    asm("{ .reg .u64 t; cvta.to.shared.u64 t, %1; cvt.u32.u64 %0, t; }" : "=r"(a) : "l"(p));
    return a;
}
__device__ __forceinline__ void cp16(uint32_t dst, const void* src) {
    asm volatile("cp.async.cg.shared.global [%0], [%1], 16;" :: "r"(dst), "l"(src));
}
#define CP_COMMIT() asm volatile("cp.async.commit_group;" ::: "memory")
#define CP_WAIT(n)  asm volatile("cp.async.wait_group %0;" :: "n"(n) : "memory")

__device__ __forceinline__ void ldsm_x4(uint32_t addr, uint32_t r[4]) {
    asm volatile("ldmatrix.sync.aligned.m8n8.x4.shared.b16 {%0,%1,%2,%3}, [%4];"
                 : "=r"(r[0]), "=r"(r[1]), "=r"(r[2]), "=r"(r[3]) : "r"(addr));
}
__device__ __forceinline__ void ldsm_x2(uint32_t addr, uint32_t r[2]) {
    asm volatile("ldmatrix.sync.aligned.m8n8.x2.shared.b16 {%0,%1}, [%2];"
                 : "=r"(r[0]), "=r"(r[1]) : "r"(addr));
}
__device__ __forceinline__ void mma_bf16(float d[4], const uint32_t a[4], const uint32_t b[2]) {
    asm volatile("mma.sync.aligned.m16n8k16.row.col.f32.bf16.bf16.f32 "
                 "{%0,%1,%2,%3}, {%4,%5,%6,%7}, {%8,%9}, {%0,%1,%2,%3};"
                 : "+f"(d[0]), "+f"(d[1]), "+f"(d[2]), "+f"(d[3])
                 : "r"(a[0]), "r"(a[1]), "r"(a[2]), "r"(a[3]), "r"(b[0]), "r"(b[1]));
}
__device__ __forceinline__ void split_bf16(float v, __nv_bfloat16& hi, __nv_bfloat16& lo) {
    hi = __float2bfloat16_rn(v);
    lo = __float2bfloat16_rn(v - __bfloat162float(hi));
}
__device__ __forceinline__ float fast_sigmoid(float v) {
    return __fdividef(1.f, 1.f + __expf(-v));
}
__device__ __forceinline__ float fast_tanh(float v) {
    float e = __expf(-2.f * v);
    return __fdividef(1.f - e, 1.f + e);
}

// ---------------- Wih -> bf16 hi/lo ----------------
__global__ void k_w_convert(const float* __restrict__ wih) {
    size_t i = (size_t)blockIdx.x * 1024 + threadIdx.x * 4;
    #pragma unroll
    for (int j = 0; j < 4; ++j) {
        float v = wih[i + j];
        split_bf16(v, g_whi[i + j], g_wlo[i + j]);
    }
}

// ---------------- x [B][I][S] -> g_xhi/g_xlo [(s*B+b)][i] bf16 ----------------
__global__ void k_x_transpose(const float* __restrict__ x) {
    __shared__ float tile[32][33];
    int s0 = blockIdx.x * 32;
    int i0 = blockIdx.y * 32;
    int b  = blockIdx.z;
    int tx = threadIdx.x, ty = threadIdx.y;
    #pragma unroll
    for (int j = 0; j < 4; ++j)
        tile[ty + 8 * j][tx] = x[((size_t)b * ISZ + i0 + ty + 8 * j) * STEPS + s0 + tx];
    __syncthreads();
    #pragma unroll
    for (int j = 0; j < 4; ++j) {
        int s = s0 + ty + 8 * j;
        float v = tile[tx][ty + 8 * j];
        size_t o = ((size_t)s * BATCH + b) * ISZ + i0 + tx;
        split_bf16(v, g_xhi[o], g_xlo[o]);
    }
}

// ---------------- HMMA GEMM: gi = x_split @ Wih_split^T + bias_ih ----------------
#define SA 72
#define ATILE_B (128 * SA * 2)
#define GEMM_SMEM (2 * 4 * ATILE_B)

__device__ __forceinline__ void gi_issue_load(uint32_t sb, int tid, int m0, int n0,
                                              int chunk, int buf) {
    const int k0 = chunk * 64;
    const __nv_bfloat16* srcs[4] = {g_xhi, g_xlo, g_whi, g_wlo};
    const int rowbase[4] = {m0, m0, n0, n0};
    #pragma unroll
    for (int t = 0; t < 4; ++t) {
        const __nv_bfloat16* src = srcs[t];
        uint32_t dst0 = sb + buf * 4 * ATILE_B + t * ATILE_B;
        #pragma unroll
        for (int i = 0; i < 4; ++i) {
            int lin = tid + 256 * i;
            int row = lin >> 3;
            int cq  = lin & 7;
            cp16(dst0 + row * (SA * 2) + cq * 16,
                 src + (size_t)(rowbase[t] + row) * ISZ + k0 + cq * 8);
        }
    }
}

__global__ void __launch_bounds__(256, 1) k_gemm_gi(const float* __restrict__ bias_ih) {
    extern __shared__ char smem[];
    uint32_t sb = smem_to_u32(smem);
    const int tid = threadIdx.x;
    const int lane = tid & 31;
    const int wid = tid >> 5;
    const int wm = wid & 3;
    const int wn = wid >> 2;
    const int m0 = blockIdx.y * 128;
    const int n0 = blockIdx.x * 128;

    const int t4 = lane >> 3;
    const int arow = (t4 & 1) * 8 + (lane & 7);
    const int acol = (t4 >> 1) * 8;
    const int brow = (t4 >> 1) * 8 + (lane & 7);
    const int bcol = (t4 & 1) * 8;

    float acc[2][8][4];
    #pragma unroll
    for (int i = 0; i < 2; ++i)
        #pragma unroll
        for (int j = 0; j < 8; ++j)
            #pragma unroll
            for (int v = 0; v < 4; ++v) acc[i][j][v] = 0.f;

    gi_issue_load(sb, tid, m0, n0, 0, 0);
    CP_COMMIT();

    for (int c = 0; c < 8; ++c) {
        if (c < 7) {
            gi_issue_load(sb, tid, m0, n0, c + 1, (c + 1) & 1);
            CP_COMMIT();
            CP_WAIT(1);
        } else {
            CP_WAIT(0);
        }
        __syncthreads();
        const int buf = c & 1;
        const uint32_t bufb = sb + buf * 4 * ATILE_B;

        #pragma unroll
        for (int kk = 0; kk < 64; kk += 16) {
            uint32_t Ah[2][4], Al[2][4], Bh[8][2], Bl[8][2];
            #pragma unroll
            for (int mt = 0; mt < 2; ++mt) {
                uint32_t r = (wm * 32 + mt * 16 + arow) * (SA * 2) + (kk + acol) * 2;
                ldsm_x4(bufb + 0 * ATILE_B + r, Ah[mt]);
                ldsm_x4(bufb + 1 * ATILE_B + r, Al[mt]);
            }
            #pragma unroll
            for (int pt = 0; pt < 4; ++pt) {
                uint32_t r = (wn * 64 + pt * 16 + brow) * (SA * 2) + (kk + bcol) * 2;
                uint32_t q[4];
                ldsm_x4(bufb + 2 * ATILE_B + r, q);
                Bh[2 * pt][0] = q[0]; Bh[2 * pt][1] = q[1];
                Bh[2 * pt + 1][0] = q[2]; Bh[2 * pt + 1][1] = q[3];
                ldsm_x4(bufb + 3 * ATILE_B + r, q);
                Bl[2 * pt][0] = q[0]; Bl[2 * pt][1] = q[1];
                Bl[2 * pt + 1][0] = q[2]; Bl[2 * pt + 1][1] = q[3];
            }
            #pragma unroll
            for (int mt = 0; mt < 2; ++mt)
                #pragma unroll
                for (int nt = 0; nt < 8; ++nt) {
                    mma_bf16(acc[mt][nt], Ah[mt], Bh[nt]);
                    mma_bf16(acc[mt][nt], Ah[mt], Bl[nt]);
                    mma_bf16(acc[mt][nt], Al[mt], Bh[nt]);
                }
        }
        __syncthreads();
    }

    #pragma unroll
    for (int nt = 0; nt < 8; ++nt) {
        int n_base = n0 + wn * 64 + nt * 8 + (lane & 3) * 2;
        float2 bb = *(const float2*)(bias_ih + n_base);
        #pragma unroll
        for (int mt = 0; mt < 2; ++mt) {
            int m_base = m0 + wm * 32 + mt * 16 + (lane >> 2);
            float2 v0, v1;
            v0.x = acc[mt][nt][0] + bb.x;
            v0.y = acc[mt][nt][1] + bb.y;
            v1.x = acc[mt][nt][2] + bb.x;
            v1.y = acc[mt][nt][3] + bb.y;
            *(float2*)(g_gi + (size_t)m_base * GH + n_base) = v0;
            *(float2*)(g_gi + (size_t)(m_base + 8) * GH + n_base) = v1;
        }
    }
}

// ---------------- persistent GRU recurrence v5: HMMA + per-bg barrier ----------------
// 4 independent barrier chains (one per 64-row batch group, 32 CTAs each).
// Release/acquire atomics; no cross-bg coupling exists in the dataflow.
__device__ __forceinline__ void gridbar_bg(int bg, unsigned target) {
    __syncthreads();
    if (threadIdx.x == 0) {
        unsigned a;
        asm volatile("atom.add.release.gpu.global.u32 %0, [%1], 1;"
                     : "=r"(a) : "l"(&g_bg_cnt[bg]) : "memory");
        if (a == 31u) {
            asm volatile("st.global.relaxed.gpu.u32 [%0], 0;" :: "l"(&g_bg_cnt[bg]) : "memory");
            asm volatile("st.global.release.gpu.u32 [%0], %1;"
                         :: "l"(&g_bg_gen[bg]), "r"(target) : "memory");
        } else {
            unsigned g;
            do {
                asm volatile("ld.global.acquire.gpu.u32 %0, [%1];"
                             : "=r"(g) : "l"(&g_bg_gen[bg]) : "memory");
            } while ((int)(g - target) < 0);
        }
    }
    __syncthreads();
}

#define A_HI 0
#define A_LO 65536
#define B_HI 131072
#define BSTR 520
#define B_LO (B_HI + 48 * BSTR * 2)
#define REC2_SMEM (B_LO + 48 * BSTR * 2)
#define GH_STR 50

__device__ __forceinline__ uint32_t a_off(int row, int kb) {
    uint32_t u = ((uint32_t)kb >> 3) ^ (row & 7);
    return (uint32_t)row * 1024 + u * 16;
}

__global__ void __launch_bounds__(256, 1) k_gru_recur(
    const float* __restrict__ whh, const float* __restrict__ bhh,
    float* __restrict__ out)
{
    extern __shared__ char smem[];
    uint32_t sb = smem_to_u32(smem);
    float* gh = (float*)smem;

    const int cta = blockIdx.x;
    const int cg  = cta & 31;
    const int bg0 = cta >> 5;
    const int tid = threadIdx.x;
    const int lane = tid & 31;
    const int wid = tid >> 5;
    const int wm = wid & 3;
    const int wn = wid >> 2;

    const int t4 = lane >> 3;
    const int arow = (t4 & 1) * 8 + (lane & 7);
    const int acol = (t4 >> 1) * 8;
    const int brow = (t4 >> 1) * 8 + (lane & 7);
    const int bcol = (t4 & 1) * 8;
    const int brow2 = lane & 7;
    const int bcol2 = ((lane >> 3) & 1) * 8;

    for (int idx = tid; idx < 48 * 128; idx += 256) {
        int r = idx >> 7;
        int kq = idx & 127;
        int g = r >> 4, c = r & 15;
        float4 v = *(const float4*)(whh + (size_t)(g * HID + cg * 16 + c) * HID + kq * 4);
        __nv_bfloat16 hi[4], lo[4];
        split_bf16(v.x, hi[0], lo[0]);
        split_bf16(v.y, hi[1], lo[1]);
        split_bf16(v.z, hi[2], lo[2]);
        split_bf16(v.w, hi[3], lo[3]);
        *(uint2*)(smem + B_HI + r * (BSTR * 2) + kq * 8) = *(uint2*)hi;
        *(uint2*)(smem + B_LO + r * (BSTR * 2) + kq * 8) = *(uint2*)lo;
    }

    const int gb = tid >> 2;
    const int cq = tid & 3;
    const int c0 = cq * 4;
    const int gcol0 = cg * 16 + c0;
    float br[4], bz[4], bn[4];
    #pragma unroll
    for (int i = 0; i < 4; ++i) {
        br[i] = bhh[gcol0 + i];
        bz[i] = bhh[HID + gcol0 + i];
        bn[i] = bhh[2 * HID + gcol0 + i];
    }

    {
        uint4 z = make_uint4(0, 0, 0, 0);
        *(uint4*)((char*)g_hbf[0] + ((size_t)cta * 256 + tid) * 16) = z;
    }
    float h_old[4] = {0.f, 0.f, 0.f, 0.f};

    unsigned base;
    asm volatile("ld.global.acquire.gpu.u32 %0, [%1];"
                 : "=r"(base) : "l"(&g_bg_gen[bg0]) : "memory");
    gridbar_bg(bg0, base + 1);

    const uint32_t bhi = sb + B_HI;
    const uint32_t blo = sb + B_LO;
    const int nb = wn * 24;
    const int bglob = bg0 * 64 + gb;

    for (int s = 0; s < STEPS; ++s) {
        const int cur = s & 1, nxt = cur ^ 1;
        const __nv_bfloat16* hsrc_hi = g_hbf[cur][0];
        const __nv_bfloat16* hsrc_lo = g_hbf[cur][1];

        // issue ALL 4 A chunks up front (deep pipeline; loads hide under MMA)
        #pragma unroll
        for (int pre = 0; pre < 4; ++pre) {
            #pragma unroll
            for (int i = 0; i < 8; ++i) {
                int lin = tid + 256 * i;
                int half = lin >> 10;
                int r = lin & 1023;
                int row = r >> 4;
                int kb = pre * 128 + (r & 15) * 8;
                const __nv_bfloat16* src = half ? hsrc_lo : hsrc_hi;
                cp16(sb + (half ? A_LO : A_HI) + a_off(row, kb),
                     src + (size_t)(bg0 * 64 + row) * HID + kb);
            }
            CP_COMMIT();
        }

        const float* gip = g_gi + ((size_t)s * BATCH + bglob) * GH;
        float4 gr4 = __ldcg((const float4*)(gip + gcol0));
        float4 gz4 = __ldcg((const float4*)(gip + HID + gcol0));
        float4 gn4 = __ldcg((const float4*)(gip + 2 * HID + gcol0));

        float acc[3][4];
        #pragma unroll
        for (int j = 0; j < 3; ++j)
            #pragma unroll
            for (int v = 0; v < 4; ++v) acc[j][v] = 0.f;

        #pragma unroll
        for (int kc = 0; kc < 4; ++kc) {
            if (kc == 0)      CP_WAIT(3);
            else if (kc == 1) CP_WAIT(2);
            else if (kc == 2) CP_WAIT(1);
            else              CP_WAIT(0);
            __syncthreads();

            #pragma unroll
            for (int t = 0; t < 8; ++t) {
                const int kk = kc * 128 + t * 16;
                uint32_t Ah[4], Al[4], Bh[3][2], Bl[3][2];
                {
                    int rr = wm * 16 + arow;
                    ldsm_x4(sb + A_HI + a_off(rr, kk + acol), Ah);
                    ldsm_x4(sb + A_LO + a_off(rr, kk + acol), Al);
                }
                {
                    uint32_t q[4];
                    uint32_t r16 = (nb + brow) * (BSTR * 2) + (kk + bcol) * 2;
                    ldsm_x4(bhi + r16, q);
                    Bh[0][0] = q[0]; Bh[0][1] = q[1];
                    Bh[1][0] = q[2]; Bh[1][1] = q[3];
                    ldsm_x4(blo + r16, q);
                    Bl[0][0] = q[0]; Bl[0][1] = q[1];
                    Bl[1][0] = q[2]; Bl[1][1] = q[3];
                    uint32_t r8 = (nb + 16 + brow2) * (BSTR * 2) + (kk + bcol2) * 2;
                    ldsm_x2(bhi + r8, Bh[2]);
                    ldsm_x2(blo + r8, Bl[2]);
                }
                #pragma unroll
                for (int nt = 0; nt < 3; ++nt) {
                    mma_bf16(acc[nt], Ah, Bh[nt]);
                    mma_bf16(acc[nt], Ah, Bl[nt]);
                    mma_bf16(acc[nt], Al, Bh[nt]);
                }
            }
        }
        __syncthreads();   // A reads done -> safe to overwrite with gh

        {
            int row0 = wm * 16 + (lane >> 2);
            int col0 = nb + (lane & 3) * 2;
            #pragma unroll
            for (int nt = 0; nt < 3; ++nt) {
                *(float2*)(gh + row0 * GH_STR + col0 + nt * 8) = make_float2(acc[nt][0], acc[nt][1]);
                *(float2*)(gh + (row0 + 8) * GH_STR + col0 + nt * 8) = make_float2(acc[nt][2], acc[nt][3]);
            }
        }
        __syncthreads();

        {
            float grv[4] = {gr4.x, gr4.y, gr4.z, gr4.w};
            float gzv[4] = {gz4.x, gz4.y, gz4.z, gz4.w};
            float gnv[4] = {gn4.x, gn4.y, gn4.z, gn4.w};
            __nv_bfloat16 hi4[4], lo4[4];
            float hnew4[4];
            #pragma unroll
            for (int i = 0; i < 4; ++i) {
                int c = c0 + i;
                float ar = gh[gb * GH_STR + 0 * 16 + c];
                float az = gh[gb * GH_STR + 1 * 16 + c];
                float an = gh[gb * GH_STR + 2 * 16 + c];
                float rg = fast_sigmoid(grv[i] + ar + br[i]);
                float zg = fast_sigmoid(gzv[i] + az + bz[i]);
                float ng = fast_tanh(gnv[i] + rg * (an + bn[i]));
                float hnew = (1.f - zg) * ng + zg * h_old[i];
                h_old[i] = hnew;
                hnew4[i] = hnew;
                split_bf16(hnew, hi4[i], lo4[i]);
            }
            size_t ho = (size_t)bglob * HID + gcol0;
            *(uint2*)(g_hbf[nxt][0] + ho) = *(uint2*)hi4;
            *(uint2*)(g_hbf[nxt][1] + ho) = *(uint2*)lo4;
            if (s == STEPS - 1)
                *(float4*)(out + ho) = *(float4*)hnew4;
        }

        gridbar_bg(bg0, base + 2 + s);
    }
}

// ---------------- launcher ----------------
extern "C" void kernel_launch(void* const* d_in, const int* in_sizes, int n_in,
                              void* d_out, int out_size) {
    const float* x   = (const float*)d_in[0];
    const float* wih = (const float*)d_in[1];
    const float* whh = (const float*)d_in[2];
    const float* bih = (const float*)d_in[3];
    const float* bhh = (const float*)d_in[4];
    float* out = (float*)d_out;

    cudaFuncSetAttribute(k_gru_recur, cudaFuncAttributeMaxDynamicSharedMemorySize,
                         REC2_SMEM);
    cudaFuncSetAttribute(k_gemm_gi, cudaFuncAttributeMaxDynamicSharedMemorySize,
                         GEMM_SMEM);

    k_w_convert<<<(GH * ISZ) / 1024, 256>>>(wih);
    k_x_transpose<<<dim3(STEPS / 32, ISZ / 32, BATCH), dim3(32, 8)>>>(x);
    k_gemm_gi<<<dim3(GH / 128, MROWS / 128), 256, GEMM_SMEM>>>(bih);
    k_gru_recur<<<NCTA, 256, REC2_SMEM>>>(whh, bhh, out);
}

// round 8
// speedup vs baseline: 5.3818x; 1.2561x over previous
#include <cuda_runtime.h>
#include <cuda_fp16.h>
#include <cstdint>

#define BATCH 256
#define ISZ   512
#define STEPS 256
#define HID   512
#define GH    1536
#define NCTA  128
#define MROWS (STEPS * BATCH)     // 65536

// ---------------- scratch ----------------
__device__ __half g_x16[(size_t)MROWS * ISZ];
__device__ __half g_w16hi[(size_t)GH * ISZ];
__device__ __half g_w16lo[(size_t)GH * ISZ];
__device__ float g_gi[(size_t)MROWS * GH];
__device__ __half g_h16[2][BATCH * HID];
__device__ unsigned g_bg_cnt[4];
__device__ unsigned g_bg_gen[4];

// ---------------- helpers ----------------
__device__ __forceinline__ uint32_t smem_to_u32(const void* p) {
    uint32_t a;
    asm("{ .reg .u64 t; cvta.to.shared.u64 t, %1; cvt.u32.u64 %0, t; }" : "=r"(a) : "l"(p));
    return a;
}
__device__ __forceinline__ void cp16(uint32_t dst, const void* src) {
    asm volatile("cp.async.cg.shared.global [%0], [%1], 16;" :: "r"(dst), "l"(src));
}
#define CP_COMMIT() asm volatile("cp.async.commit_group;" ::: "memory")
#define CP_WAIT(n)  asm volatile("cp.async.wait_group %0;" :: "n"(n) : "memory")

__device__ __forceinline__ void ldsm_x4(uint32_t addr, uint32_t r[4]) {
    asm volatile("ldmatrix.sync.aligned.m8n8.x4.shared.b16 {%0,%1,%2,%3}, [%4];"
                 : "=r"(r[0]), "=r"(r[1]), "=r"(r[2]), "=r"(r[3]) : "r"(addr));
}
__device__ __forceinline__ void ldsm_x2(uint32_t addr, uint32_t r[2]) {
    asm volatile("ldmatrix.sync.aligned.m8n8.x2.shared.b16 {%0,%1}, [%2];"
                 : "=r"(r[0]), "=r"(r[1]) : "r"(addr));
}
__device__ __forceinline__ void mma_f16(float d[4], const uint32_t a[4], const uint32_t b[2]) {
    asm volatile("mma.sync.aligned.m16n8k16.row.col.f32.f16.f16.f32 "
                 "{%0,%1,%2,%3}, {%4,%5,%6,%7}, {%8,%9}, {%0,%1,%2,%3};"
                 : "+f"(d[0]), "+f"(d[1]), "+f"(d[2]), "+f"(d[3])
                 : "r"(a[0]), "r"(a[1]), "r"(a[2]), "r"(a[3]), "r"(b[0]), "r"(b[1]));
}
__device__ __forceinline__ void split_f16(float v, __half& hi, __half& lo) {
    hi = __float2half_rn(v);
    lo = __float2half_rn(v - __half2float(hi));
}
__device__ __forceinline__ float fast_sigmoid(float v) {
    return __fdividef(1.f, 1.f + __expf(-v));
}
__device__ __forceinline__ float fast_tanh(float v) {
    float e = __expf(-2.f * v);
    return __fdividef(1.f - e, 1.f + e);
}

// ---------------- Wih -> fp16 hi/lo ----------------
__global__ void k_w_convert(const float* __restrict__ wih) {
    size_t i = (size_t)blockIdx.x * 1024 + threadIdx.x * 4;
    #pragma unroll
    for (int j = 0; j < 4; ++j) {
        float v = wih[i + j];
        split_f16(v, g_w16hi[i + j], g_w16lo[i + j]);
    }
}

// ---------------- x [B][I][S] -> g_x16 [(s*B+b)][i] fp16 ----------------
__global__ void k_x_transpose(const float* __restrict__ x) {
    __shared__ float tile[32][33];
    int s0 = blockIdx.x * 32;
    int i0 = blockIdx.y * 32;
    int b  = blockIdx.z;
    int tx = threadIdx.x, ty = threadIdx.y;
    #pragma unroll
    for (int j = 0; j < 4; ++j)
        tile[ty + 8 * j][tx] = x[((size_t)b * ISZ + i0 + ty + 8 * j) * STEPS + s0 + tx];
    __syncthreads();
    #pragma unroll
    for (int j = 0; j < 4; ++j) {
        int s = s0 + ty + 8 * j;
        float v = tile[tx][ty + 8 * j];
        g_x16[((size_t)s * BATCH + b) * ISZ + i0 + tx] = __float2half_rn(v);
    }
}

// ---------------- HMMA GEMM: gi = x(fp16) @ Wih(hi+lo)^T + bias_ih ----------------
// 2-MMA split: x*Whi + x*Wlo. 3 tiles per buffer (A, Bhi, Blo).
#define SA 72
#define ATILE_B (128 * SA * 2)
#define GEMM_SMEM (2 * 3 * ATILE_B)

__device__ __forceinline__ void gi_issue_load(uint32_t sb, int tid, int m0, int n0,
                                              int chunk, int buf) {
    const int k0 = chunk * 64;
    const __half* srcs[3] = {g_x16, g_w16hi, g_w16lo};
    const int rowbase[3] = {m0, n0, n0};
    #pragma unroll
    for (int t = 0; t < 3; ++t) {
        const __half* src = srcs[t];
        uint32_t dst0 = sb + buf * 3 * ATILE_B + t * ATILE_B;
        #pragma unroll
        for (int i = 0; i < 4; ++i) {
            int lin = tid + 256 * i;
            int row = lin >> 3;
            int cq  = lin & 7;
            cp16(dst0 + row * (SA * 2) + cq * 16,
                 src + (size_t)(rowbase[t] + row) * ISZ + k0 + cq * 8);
        }
    }
}

__global__ void __launch_bounds__(256, 1) k_gemm_gi(const float* __restrict__ bias_ih) {
    extern __shared__ char smem[];
    uint32_t sb = smem_to_u32(smem);
    const int tid = threadIdx.x;
    const int lane = tid & 31;
    const int wid = tid >> 5;
    const int wm = wid & 3;
    const int wn = wid >> 2;
    const int m0 = blockIdx.y * 128;
    const int n0 = blockIdx.x * 128;

    const int t4 = lane >> 3;
    const int arow = (t4 & 1) * 8 + (lane & 7);
    const int acol = (t4 >> 1) * 8;
    const int brow = (t4 >> 1) * 8 + (lane & 7);
    const int bcol = (t4 & 1) * 8;

    float acc[2][8][4];
    #pragma unroll
    for (int i = 0; i < 2; ++i)
        #pragma unroll
        for (int j = 0; j < 8; ++j)
            #pragma unroll
            for (int v = 0; v < 4; ++v) acc[i][j][v] = 0.f;

    gi_issue_load(sb, tid, m0, n0, 0, 0);
    CP_COMMIT();

    for (int c = 0; c < 8; ++c) {
        if (c < 7) {
            gi_issue_load(sb, tid, m0, n0, c + 1, (c + 1) & 1);
            CP_COMMIT();
            CP_WAIT(1);
        } else {
            CP_WAIT(0);
        }
        __syncthreads();
        const int buf = c & 1;
        const uint32_t bufb = sb + buf * 3 * ATILE_B;

        #pragma unroll
        for (int kk = 0; kk < 64; kk += 16) {
            uint32_t Ax[2][4], Bh[8][2], Bl[8][2];
            #pragma unroll
            for (int mt = 0; mt < 2; ++mt) {
                uint32_t r = (wm * 32 + mt * 16 + arow) * (SA * 2) + (kk + acol) * 2;
                ldsm_x4(bufb + 0 * ATILE_B + r, Ax[mt]);
            }
            #pragma unroll
            for (int pt = 0; pt < 4; ++pt) {
                uint32_t r = (wn * 64 + pt * 16 + brow) * (SA * 2) + (kk + bcol) * 2;
                uint32_t q[4];
                ldsm_x4(bufb + 1 * ATILE_B + r, q);
                Bh[2 * pt][0] = q[0]; Bh[2 * pt][1] = q[1];
                Bh[2 * pt + 1][0] = q[2]; Bh[2 * pt + 1][1] = q[3];
                ldsm_x4(bufb + 2 * ATILE_B + r, q);
                Bl[2 * pt][0] = q[0]; Bl[2 * pt][1] = q[1];
                Bl[2 * pt + 1][0] = q[2]; Bl[2 * pt + 1][1] = q[3];
            }
            #pragma unroll
            for (int mt = 0; mt < 2; ++mt)
                #pragma unroll
                for (int nt = 0; nt < 8; ++nt) {
                    mma_f16(acc[mt][nt], Ax[mt], Bh[nt]);
                    mma_f16(acc[mt][nt], Ax[mt], Bl[nt]);
                }
        }
        __syncthreads();
    }

    #pragma unroll
    for (int nt = 0; nt < 8; ++nt) {
        int n_base = n0 + wn * 64 + nt * 8 + (lane & 3) * 2;
        float2 bb = *(const float2*)(bias_ih + n_base);
        #pragma unroll
        for (int mt = 0; mt < 2; ++mt) {
            int m_base = m0 + wm * 32 + mt * 16 + (lane >> 2);
            float2 v0, v1;
            v0.x = acc[mt][nt][0] + bb.x;
            v0.y = acc[mt][nt][1] + bb.y;
            v1.x = acc[mt][nt][2] + bb.x;
            v1.y = acc[mt][nt][3] + bb.y;
            *(float2*)(g_gi + (size_t)m_base * GH + n_base) = v0;
            *(float2*)(g_gi + (size_t)(m_base + 8) * GH + n_base) = v1;
        }
    }
}

// ---------------- persistent GRU recurrence v6: fp16 2-MMA ----------------
__device__ __forceinline__ void gridbar_bg(int bg, unsigned target) {
    __syncthreads();
    if (threadIdx.x == 0) {
        unsigned a;
        asm volatile("atom.add.release.gpu.global.u32 %0, [%1], 1;"
                     : "=r"(a) : "l"(&g_bg_cnt[bg]) : "memory");
        if (a == 31u) {
            asm volatile("st.global.relaxed.gpu.u32 [%0], 0;" :: "l"(&g_bg_cnt[bg]) : "memory");
            asm volatile("st.global.release.gpu.u32 [%0], %1;"
                         :: "l"(&g_bg_gen[bg]), "r"(target) : "memory");
        } else {
            unsigned g;
            do {
                asm volatile("ld.global.acquire.gpu.u32 %0, [%1];"
                             : "=r"(g) : "l"(&g_bg_gen[bg]) : "memory");
            } while ((int)(g - target) < 0);
        }
    }
    __syncthreads();
}

#define A_OFF 0
#define B_HI 65536                       // A: 64 rows x 1024 B
#define BSTR 520
#define B_LO (B_HI + 48 * BSTR * 2)
#define REC2_SMEM (B_LO + 48 * BSTR * 2)
#define GH_STR 50

__device__ __forceinline__ uint32_t a_off(int row, int kb) {
    uint32_t u = ((uint32_t)kb >> 3) ^ (row & 7);
    return (uint32_t)row * 1024 + u * 16;
}

__global__ void __launch_bounds__(256, 1) k_gru_recur(
    const float* __restrict__ whh, const float* __restrict__ bhh,
    float* __restrict__ out)
{
    extern __shared__ char smem[];
    uint32_t sb = smem_to_u32(smem);
    float* gh = (float*)smem;            // reuses A region post-MMA

    const int cta = blockIdx.x;
    const int cg  = cta & 31;
    const int bg0 = cta >> 5;
    const int tid = threadIdx.x;
    const int lane = tid & 31;
    const int wid = tid >> 5;
    const int wm = wid & 3;
    const int wn = wid >> 2;

    const int t4 = lane >> 3;
    const int arow = (t4 & 1) * 8 + (lane & 7);
    const int acol = (t4 >> 1) * 8;
    const int brow = (t4 >> 1) * 8 + (lane & 7);
    const int bcol = (t4 & 1) * 8;
    const int brow2 = lane & 7;
    const int bcol2 = ((lane >> 3) & 1) * 8;

    // resident Whh slice -> fp16 hi/lo
    for (int idx = tid; idx < 48 * 128; idx += 256) {
        int r = idx >> 7;
        int kq = idx & 127;
        int g = r >> 4, c = r & 15;
        float4 v = *(const float4*)(whh + (size_t)(g * HID + cg * 16 + c) * HID + kq * 4);
        __half hi[4], lo[4];
        split_f16(v.x, hi[0], lo[0]);
        split_f16(v.y, hi[1], lo[1]);
        split_f16(v.z, hi[2], lo[2]);
        split_f16(v.w, hi[3], lo[3]);
        *(uint2*)(smem + B_HI + r * (BSTR * 2) + kq * 8) = *(uint2*)hi;
        *(uint2*)(smem + B_LO + r * (BSTR * 2) + kq * 8) = *(uint2*)lo;
    }

    const int gb = tid >> 2;
    const int cq = tid & 3;
    const int c0 = cq * 4;
    const int gcol0 = cg * 16 + c0;
    float br[4], bz[4], bn[4];
    #pragma unroll
    for (int i = 0; i < 4; ++i) {
        br[i] = bhh[gcol0 + i];
        bz[i] = bhh[HID + gcol0 + i];
        bn[i] = bhh[2 * HID + gcol0 + i];
    }

    {   // zero h fp16 buffer 0: 256KB total = 32768 threads x 8B
        uint2 z = make_uint2(0, 0);
        *(uint2*)((char*)g_h16[0] + ((size_t)cta * 256 + tid) * 8) = z;
    }
    float h_old[4] = {0.f, 0.f, 0.f, 0.f};

    unsigned base;
    asm volatile("ld.global.acquire.gpu.u32 %0, [%1];"
                 : "=r"(base) : "l"(&g_bg_gen[bg0]) : "memory");
    gridbar_bg(bg0, base + 1);

    const uint32_t bhi = sb + B_HI;
    const uint32_t blo = sb + B_LO;
    const int nb = wn * 24;
    const int bglob = bg0 * 64 + gb;

    for (int s = 0; s < STEPS; ++s) {
        const int cur = s & 1, nxt = cur ^ 1;
        const __half* hsrc = g_h16[cur];

        // issue all 4 A chunks (each 64 rows x 128 k halfs = 1024 cp16)
        #pragma unroll
        for (int pre = 0; pre < 4; ++pre) {
            #pragma unroll
            for (int i = 0; i < 4; ++i) {
                int lin = tid + 256 * i;            // 0..1023
                int row = lin >> 4;
                int kb = pre * 128 + (lin & 15) * 8;
                cp16(sb + A_OFF + a_off(row, kb),
                     hsrc + (size_t)(bg0 * 64 + row) * HID + kb);
            }
            CP_COMMIT();
        }

        const float* gip = g_gi + ((size_t)s * BATCH + bglob) * GH;
        float4 gr4 = __ldcg((const float4*)(gip + gcol0));
        float4 gz4 = __ldcg((const float4*)(gip + HID + gcol0));
        float4 gn4 = __ldcg((const float4*)(gip + 2 * HID + gcol0));

        float acc[3][4];
        #pragma unroll
        for (int j = 0; j < 3; ++j)
            #pragma unroll
            for (int v = 0; v < 4; ++v) acc[j][v] = 0.f;

        #pragma unroll
        for (int kc = 0; kc < 4; ++kc) {
            if (kc == 0)      CP_WAIT(3);
            else if (kc == 1) CP_WAIT(2);
            else if (kc == 2) CP_WAIT(1);
            else              CP_WAIT(0);
            __syncthreads();

            #pragma unroll
            for (int t = 0; t < 8; ++t) {
                const int kk = kc * 128 + t * 16;
                uint32_t Ax[4], Bh[3][2], Bl[3][2];
                {
                    int rr = wm * 16 + arow;
                    ldsm_x4(sb + A_OFF + a_off(rr, kk + acol), Ax);
                }
                {
                    uint32_t q[4];
                    uint32_t r16 = (nb + brow) * (BSTR * 2) + (kk + bcol) * 2;
                    ldsm_x4(bhi + r16, q);
                    Bh[0][0] = q[0]; Bh[0][1] = q[1];
                    Bh[1][0] = q[2]; Bh[1][1] = q[3];
                    ldsm_x4(blo + r16, q);
                    Bl[0][0] = q[0]; Bl[0][1] = q[1];
                    Bl[1][0] = q[2]; Bl[1][1] = q[3];
                    uint32_t r8 = (nb + 16 + brow2) * (BSTR * 2) + (kk + bcol2) * 2;
                    ldsm_x2(bhi + r8, Bh[2]);
                    ldsm_x2(blo + r8, Bl[2]);
                }
                #pragma unroll
                for (int nt = 0; nt < 3; ++nt) {
                    mma_f16(acc[nt], Ax, Bh[nt]);
                    mma_f16(acc[nt], Ax, Bl[nt]);
                }
            }
        }
        __syncthreads();   // A reads done -> safe to overwrite with gh

        {
            int row0 = wm * 16 + (lane >> 2);
            int col0 = nb + (lane & 3) * 2;
            #pragma unroll
            for (int nt = 0; nt < 3; ++nt) {
                *(float2*)(gh + row0 * GH_STR + col0 + nt * 8) = make_float2(acc[nt][0], acc[nt][1]);
                *(float2*)(gh + (row0 + 8) * GH_STR + col0 + nt * 8) = make_float2(acc[nt][2], acc[nt][3]);
            }
        }
        __syncthreads();

        {
            float grv[4] = {gr4.x, gr4.y, gr4.z, gr4.w};
            float gzv[4] = {gz4.x, gz4.y, gz4.z, gz4.w};
            float gnv[4] = {gn4.x, gn4.y, gn4.z, gn4.w};
            __half h16[4];
            float hnew4[4];
            #pragma unroll
            for (int i = 0; i < 4; ++i) {
                int c = c0 + i;
                float ar = gh[gb * GH_STR + 0 * 16 + c];
                float az = gh[gb * GH_STR + 1 * 16 + c];
                float an = gh[gb * GH_STR + 2 * 16 + c];
                float rg = fast_sigmoid(grv[i] + ar + br[i]);
                float zg = fast_sigmoid(gzv[i] + az + bz[i]);
                float ng = fast_tanh(gnv[i] + rg * (an + bn[i]));
                float hnew = (1.f - zg) * ng + zg * h_old[i];
                h_old[i] = hnew;               // exact fp32 state in registers
                hnew4[i] = hnew;
                h16[i] = __float2half_rn(hnew);
            }
            size_t ho = (size_t)bglob * HID + gcol0;
            *(uint2*)(g_h16[nxt] + ho) = *(uint2*)h16;
            if (s == STEPS - 1)
                *(float4*)(out + ho) = *(float4*)hnew4;
        }

        gridbar_bg(bg0, base + 2 + s);
    }
}

// ---------------- launcher ----------------
extern "C" void kernel_launch(void* const* d_in, const int* in_sizes, int n_in,
                              void* d_out, int out_size) {
    const float* x   = (const float*)d_in[0];
    const float* wih = (const float*)d_in[1];
    const float* whh = (const float*)d_in[2];
    const float* bih = (const float*)d_in[3];
    const float* bhh = (const float*)d_in[4];
    float* out = (float*)d_out;

    cudaFuncSetAttribute(k_gru_recur, cudaFuncAttributeMaxDynamicSharedMemorySize,
                         REC2_SMEM);
    cudaFuncSetAttribute(k_gemm_gi, cudaFuncAttributeMaxDynamicSharedMemorySize,
                         GEMM_SMEM);

    k_w_convert<<<(GH * ISZ) / 1024, 256>>>(wih);
    k_x_transpose<<<dim3(STEPS / 32, ISZ / 32, BATCH), dim3(32, 8)>>>(x);
    k_gemm_gi<<<dim3(GH / 128, MROWS / 128), 256, GEMM_SMEM>>>(bih);
    k_gru_recur<<<NCTA, 256, REC2_SMEM>>>(whh, bhh, out);
}

// round 9
// speedup vs baseline: 7.3099x; 1.3583x over previous
#include <cuda_runtime.h>
#include <cuda_fp16.h>
#include <cstdint>

#define BATCH 256
#define ISZ   512
#define STEPS 256
#define HID   512
#define GH    1536
#define NCTA  128
#define MROWS (STEPS * BATCH)     // 65536

// ---------------- scratch ----------------
__device__ __half g_x16[(size_t)MROWS * ISZ];
__device__ __half g_w16[(size_t)GH * ISZ];
__device__ float g_gi[(size_t)MROWS * GH];
__device__ __half g_h16[2][BATCH * HID];
__device__ unsigned g_bg_cnt[4];
__device__ unsigned g_bg_gen[4];

// ---------------- helpers ----------------
__device__ __forceinline__ uint32_t smem_to_u32(const void* p) {
    uint32_t a;
    asm("{ .reg .u64 t; cvta.to.shared.u64 t, %1; cvt.u32.u64 %0, t; }" : "=r"(a) : "l"(p));
    return a;
}
__device__ __forceinline__ void cp16(uint32_t dst, const void* src) {
    asm volatile("cp.async.cg.shared.global [%0], [%1], 16;" :: "r"(dst), "l"(src));
}
#define CP_COMMIT() asm volatile("cp.async.commit_group;" ::: "memory")
#define CP_WAIT(n)  asm volatile("cp.async.wait_group %0;" :: "n"(n) : "memory")

__device__ __forceinline__ void ldsm_x4(uint32_t addr, uint32_t r[4]) {
    asm volatile("ldmatrix.sync.aligned.m8n8.x4.shared.b16 {%0,%1,%2,%3}, [%4];"
                 : "=r"(r[0]), "=r"(r[1]), "=r"(r[2]), "=r"(r[3]) : "r"(addr));
}
__device__ __forceinline__ void ldsm_x2(uint32_t addr, uint32_t r[2]) {
    asm volatile("ldmatrix.sync.aligned.m8n8.x2.shared.b16 {%0,%1}, [%2];"
                 : "=r"(r[0]), "=r"(r[1]) : "r"(addr));
}
__device__ __forceinline__ void mma_f16(float d[4], const uint32_t a[4], const uint32_t b[2]) {
    asm volatile("mma.sync.aligned.m16n8k16.row.col.f32.f16.f16.f32 "
                 "{%0,%1,%2,%3}, {%4,%5,%6,%7}, {%8,%9}, {%0,%1,%2,%3};"
                 : "+f"(d[0]), "+f"(d[1]), "+f"(d[2]), "+f"(d[3])
                 : "r"(a[0]), "r"(a[1]), "r"(a[2]), "r"(a[3]), "r"(b[0]), "r"(b[1]));
}
__device__ __forceinline__ float fast_sigmoid(float v) {
    return __fdividef(1.f, 1.f + __expf(-v));
}
__device__ __forceinline__ float fast_tanh(float v) {
    float e = __expf(-2.f * v);
    return __fdividef(1.f - e, 1.f + e);
}

// ---------------- Wih -> fp16 ----------------
__global__ void k_w_convert(const float* __restrict__ wih) {
    size_t i = (size_t)blockIdx.x * 1024 + threadIdx.x * 4;
    #pragma unroll
    for (int j = 0; j < 4; ++j)
        g_w16[i + j] = __float2half_rn(wih[i + j]);
}

// ---------------- x [B][I][S] -> g_x16 [(s*B+b)][i] fp16 ----------------
__global__ void k_x_transpose(const float* __restrict__ x) {
    __shared__ float tile[32][33];
    int s0 = blockIdx.x * 32;
    int i0 = blockIdx.y * 32;
    int b  = blockIdx.z;
    int tx = threadIdx.x, ty = threadIdx.y;
    #pragma unroll
    for (int j = 0; j < 4; ++j)
        tile[ty + 8 * j][tx] = x[((size_t)b * ISZ + i0 + ty + 8 * j) * STEPS + s0 + tx];
    __syncthreads();
    #pragma unroll
    for (int j = 0; j < 4; ++j) {
        int s = s0 + ty + 8 * j;
        float v = tile[tx][ty + 8 * j];
        g_x16[((size_t)s * BATCH + b) * ISZ + i0 + tx] = __float2half_rn(v);
    }
}

// ---------------- HMMA GEMM: gi = x(fp16) @ Wih(fp16)^T + bias_ih ----------------
// Single-MMA per fragment; 2 tiles per buffer (A, B) -> 72KB smem -> 2 CTAs/SM.
#define SA 72
#define ATILE_B (128 * SA * 2)
#define GEMM_SMEM (2 * 2 * ATILE_B)

__device__ __forceinline__ void gi_issue_load(uint32_t sb, int tid, int m0, int n0,
                                              int chunk, int buf) {
    const int k0 = chunk * 64;
    const __half* srcs[2] = {g_x16, g_w16};
    const int rowbase[2] = {m0, n0};
    #pragma unroll
    for (int t = 0; t < 2; ++t) {
        const __half* src = srcs[t];
        uint32_t dst0 = sb + buf * 2 * ATILE_B + t * ATILE_B;
        #pragma unroll
        for (int i = 0; i < 4; ++i) {
            int lin = tid + 256 * i;
            int row = lin >> 3;
            int cq  = lin & 7;
            cp16(dst0 + row * (SA * 2) + cq * 16,
                 src + (size_t)(rowbase[t] + row) * ISZ + k0 + cq * 8);
        }
    }
}

__global__ void __launch_bounds__(256) k_gemm_gi(const float* __restrict__ bias_ih) {
    extern __shared__ char smem[];
    uint32_t sb = smem_to_u32(smem);
    const int tid = threadIdx.x;
    const int lane = tid & 31;
    const int wid = tid >> 5;
    const int wm = wid & 3;
    const int wn = wid >> 2;
    const int m0 = blockIdx.y * 128;
    const int n0 = blockIdx.x * 128;

    const int t4 = lane >> 3;
    const int arow = (t4 & 1) * 8 + (lane & 7);
    const int acol = (t4 >> 1) * 8;
    const int brow = (t4 >> 1) * 8 + (lane & 7);
    const int bcol = (t4 & 1) * 8;

    float acc[2][8][4];
    #pragma unroll
    for (int i = 0; i < 2; ++i)
        #pragma unroll
        for (int j = 0; j < 8; ++j)
            #pragma unroll
            for (int v = 0; v < 4; ++v) acc[i][j][v] = 0.f;

    gi_issue_load(sb, tid, m0, n0, 0, 0);
    CP_COMMIT();

    for (int c = 0; c < 8; ++c) {
        if (c < 7) {
            gi_issue_load(sb, tid, m0, n0, c + 1, (c + 1) & 1);
            CP_COMMIT();
            CP_WAIT(1);
        } else {
            CP_WAIT(0);
        }
        __syncthreads();
        const int buf = c & 1;
        const uint32_t bufb = sb + buf * 2 * ATILE_B;

        #pragma unroll
        for (int kk = 0; kk < 64; kk += 16) {
            uint32_t Ax[2][4], Bx[8][2];
            #pragma unroll
            for (int mt = 0; mt < 2; ++mt) {
                uint32_t r = (wm * 32 + mt * 16 + arow) * (SA * 2) + (kk + acol) * 2;
                ldsm_x4(bufb + 0 * ATILE_B + r, Ax[mt]);
            }
            #pragma unroll
            for (int pt = 0; pt < 4; ++pt) {
                uint32_t r = (wn * 64 + pt * 16 + brow) * (SA * 2) + (kk + bcol) * 2;
                uint32_t q[4];
                ldsm_x4(bufb + 1 * ATILE_B + r, q);
                Bx[2 * pt][0] = q[0]; Bx[2 * pt][1] = q[1];
                Bx[2 * pt + 1][0] = q[2]; Bx[2 * pt + 1][1] = q[3];
            }
            #pragma unroll
            for (int mt = 0; mt < 2; ++mt)
                #pragma unroll
                for (int nt = 0; nt < 8; ++nt)
                    mma_f16(acc[mt][nt], Ax[mt], Bx[nt]);
        }
        __syncthreads();
    }

    #pragma unroll
    for (int nt = 0; nt < 8; ++nt) {
        int n_base = n0 + wn * 64 + nt * 8 + (lane & 3) * 2;
        float2 bb = *(const float2*)(bias_ih + n_base);
        #pragma unroll
        for (int mt = 0; mt < 2; ++mt) {
            int m_base = m0 + wm * 32 + mt * 16 + (lane >> 2);
            float2 v0, v1;
            v0.x = acc[mt][nt][0] + bb.x;
            v0.y = acc[mt][nt][1] + bb.y;
            v1.x = acc[mt][nt][2] + bb.x;
            v1.y = acc[mt][nt][3] + bb.y;
            *(float2*)(g_gi + (size_t)m_base * GH + n_base) = v0;
            *(float2*)(g_gi + (size_t)(m_base + 8) * GH + n_base) = v1;
        }
    }
}

// ---------------- persistent GRU recurrence v7: fp16 single-MMA ----------------
__device__ __forceinline__ void gridbar_bg(int bg, unsigned target) {
    __syncthreads();
    if (threadIdx.x == 0) {
        unsigned a;
        asm volatile("atom.add.release.gpu.global.u32 %0, [%1], 1;"
                     : "=r"(a) : "l"(&g_bg_cnt[bg]) : "memory");
        if (a == 31u) {
            asm volatile("st.global.relaxed.gpu.u32 [%0], 0;" :: "l"(&g_bg_cnt[bg]) : "memory");
            asm volatile("st.global.release.gpu.u32 [%0], %1;"
                         :: "l"(&g_bg_gen[bg]), "r"(target) : "memory");
        } else {
            unsigned g;
            do {
                asm volatile("ld.global.acquire.gpu.u32 %0, [%1];"
                             : "=r"(g) : "l"(&g_bg_gen[bg]) : "memory");
            } while ((int)(g - target) < 0);
        }
    }
    __syncthreads();
}

#define A_OFF 0
#define B_OFF 65536                      // A: 64 rows x 1024 B
#define BSTR 520
#define GH_OFF (B_OFF + 48 * BSTR * 2)   // 115456 (separate gh region)
#define GH_STR 50
#define REC2_SMEM (GH_OFF + 64 * GH_STR * 4)   // 128256

__device__ __forceinline__ uint32_t a_off(int row, int kb) {
    uint32_t u = ((uint32_t)kb >> 3) ^ (row & 7);
    return (uint32_t)row * 1024 + u * 16;
}

__global__ void __launch_bounds__(256, 1) k_gru_recur(
    const float* __restrict__ whh, const float* __restrict__ bhh,
    float* __restrict__ out)
{
    extern __shared__ char smem[];
    uint32_t sb = smem_to_u32(smem);
    float* gh = (float*)(smem + GH_OFF);

    const int cta = blockIdx.x;
    const int cg  = cta & 31;
    const int bg0 = cta >> 5;
    const int tid = threadIdx.x;
    const int lane = tid & 31;
    const int wid = tid >> 5;
    const int wm = wid & 3;
    const int wn = wid >> 2;

    const int t4 = lane >> 3;
    const int arow = (t4 & 1) * 8 + (lane & 7);
    const int acol = (t4 >> 1) * 8;
    const int brow = (t4 >> 1) * 8 + (lane & 7);
    const int bcol = (t4 & 1) * 8;
    const int brow2 = lane & 7;
    const int bcol2 = ((lane >> 3) & 1) * 8;

    // resident Whh slice -> fp16 (single)
    for (int idx = tid; idx < 48 * 128; idx += 256) {
        int r = idx >> 7;
        int kq = idx & 127;
        int g = r >> 4, c = r & 15;
        float4 v = *(const float4*)(whh + (size_t)(g * HID + cg * 16 + c) * HID + kq * 4);
        __half h4[4];
        h4[0] = __float2half_rn(v.x);
        h4[1] = __float2half_rn(v.y);
        h4[2] = __float2half_rn(v.z);
        h4[3] = __float2half_rn(v.w);
        *(uint2*)(smem + B_OFF + r * (BSTR * 2) + kq * 8) = *(uint2*)h4;
    }

    const int gb = tid >> 2;
    const int cq = tid & 3;
    const int c0 = cq * 4;
    const int gcol0 = cg * 16 + c0;
    float br[4], bz[4], bn[4];
    #pragma unroll
    for (int i = 0; i < 4; ++i) {
        br[i] = bhh[gcol0 + i];
        bz[i] = bhh[HID + gcol0 + i];
        bn[i] = bhh[2 * HID + gcol0 + i];
    }

    {   // zero h fp16 buffer 0
        uint2 z = make_uint2(0, 0);
        *(uint2*)((char*)g_h16[0] + ((size_t)cta * 256 + tid) * 8) = z;
    }
    float h_old[4] = {0.f, 0.f, 0.f, 0.f};

    unsigned base;
    asm volatile("ld.global.acquire.gpu.u32 %0, [%1];"
                 : "=r"(base) : "l"(&g_bg_gen[bg0]) : "memory");
    gridbar_bg(bg0, base + 1);

    const uint32_t bof = sb + B_OFF;
    const int nb = wn * 24;
    const int bglob = bg0 * 64 + gb;

    for (int s = 0; s < STEPS; ++s) {
        const int cur = s & 1, nxt = cur ^ 1;
        const __half* hsrc = g_h16[cur];

        // issue all 4 A chunks
        #pragma unroll
        for (int pre = 0; pre < 4; ++pre) {
            #pragma unroll
            for (int i = 0; i < 4; ++i) {
                int lin = tid + 256 * i;
                int row = lin >> 4;
                int kb = pre * 128 + (lin & 15) * 8;
                cp16(sb + A_OFF + a_off(row, kb),
                     hsrc + (size_t)(bg0 * 64 + row) * HID + kb);
            }
            CP_COMMIT();
        }

        const float* gip = g_gi + ((size_t)s * BATCH + bglob) * GH;
        float4 gr4 = __ldcg((const float4*)(gip + gcol0));
        float4 gz4 = __ldcg((const float4*)(gip + HID + gcol0));
        float4 gn4 = __ldcg((const float4*)(gip + 2 * HID + gcol0));

        float acc[3][4];
        #pragma unroll
        for (int j = 0; j < 3; ++j)
            #pragma unroll
            for (int v = 0; v < 4; ++v) acc[j][v] = 0.f;

        #pragma unroll
        for (int kc = 0; kc < 4; ++kc) {
            if (kc == 0)      CP_WAIT(3);
            else if (kc == 1) CP_WAIT(2);
            else if (kc == 2) CP_WAIT(1);
            else              CP_WAIT(0);
            __syncthreads();

            #pragma unroll
            for (int t = 0; t < 8; ++t) {
                const int kk = kc * 128 + t * 16;
                uint32_t Ax[4], Bx[3][2];
                {
                    int rr = wm * 16 + arow;
                    ldsm_x4(sb + A_OFF + a_off(rr, kk + acol), Ax);
                }
                {
                    uint32_t q[4];
                    uint32_t r16 = (nb + brow) * (BSTR * 2) + (kk + bcol) * 2;
                    ldsm_x4(bof + r16, q);
                    Bx[0][0] = q[0]; Bx[0][1] = q[1];
                    Bx[1][0] = q[2]; Bx[1][1] = q[3];
                    uint32_t r8 = (nb + 16 + brow2) * (BSTR * 2) + (kk + bcol2) * 2;
                    ldsm_x2(bof + r8, Bx[2]);
                }
                #pragma unroll
                for (int nt = 0; nt < 3; ++nt)
                    mma_f16(acc[nt], Ax, Bx[nt]);
            }
        }

        // gh lives in its own region: no sync needed before writing own fragments
        {
            int row0 = wm * 16 + (lane >> 2);
            int col0 = nb + (lane & 3) * 2;
            #pragma unroll
            for (int nt = 0; nt < 3; ++nt) {
                *(float2*)(gh + row0 * GH_STR + col0 + nt * 8) = make_float2(acc[nt][0], acc[nt][1]);
                *(float2*)(gh + (row0 + 8) * GH_STR + col0 + nt * 8) = make_float2(acc[nt][2], acc[nt][3]);
            }
        }
        __syncthreads();

        {
            float grv[4] = {gr4.x, gr4.y, gr4.z, gr4.w};
            float gzv[4] = {gz4.x, gz4.y, gz4.z, gz4.w};
            float gnv[4] = {gn4.x, gn4.y, gn4.z, gn4.w};
            __half h16v[4];
            float hnew4[4];
            #pragma unroll
            for (int i = 0; i < 4; ++i) {
                int c = c0 + i;
                float ar = gh[gb * GH_STR + 0 * 16 + c];
                float az = gh[gb * GH_STR + 1 * 16 + c];
                float an = gh[gb * GH_STR + 2 * 16 + c];
                float rg = fast_sigmoid(grv[i] + ar + br[i]);
                float zg = fast_sigmoid(gzv[i] + az + bz[i]);
                float ng = fast_tanh(gnv[i] + rg * (an + bn[i]));
                float hnew = (1.f - zg) * ng + zg * h_old[i];
                h_old[i] = hnew;               // exact fp32 state in registers
                hnew4[i] = hnew;
                h16v[i] = __float2half_rn(hnew);
            }
            size_t ho = (size_t)bglob * HID + gcol0;
            *(uint2*)(g_h16[nxt] + ho) = *(uint2*)h16v;
            if (s == STEPS - 1)
                *(float4*)(out + ho) = *(float4*)hnew4;
        }

        gridbar_bg(bg0, base + 2 + s);
    }
}

// ---------------- launcher ----------------
extern "C" void kernel_launch(void* const* d_in, const int* in_sizes, int n_in,
                              void* d_out, int out_size) {
    const float* x   = (const float*)d_in[0];
    const float* wih = (const float*)d_in[1];
    const float* whh = (const float*)d_in[2];
    const float* bih = (const float*)d_in[3];
    const float* bhh = (const float*)d_in[4];
    float* out = (float*)d_out;

    cudaFuncSetAttribute(k_gru_recur, cudaFuncAttributeMaxDynamicSharedMemorySize,
                         REC2_SMEM);
    cudaFuncSetAttribute(k_gemm_gi, cudaFuncAttributeMaxDynamicSharedMemorySize,
                         GEMM_SMEM);

    k_w_convert<<<(GH * ISZ) / 1024, 256>>>(wih);
    k_x_transpose<<<dim3(STEPS / 32, ISZ / 32, BATCH), dim3(32, 8)>>>(x);
    k_gemm_gi<<<dim3(GH / 128, MROWS / 128), 256, GEMM_SMEM>>>(bih);
    k_gru_recur<<<NCTA, 256, REC2_SMEM>>>(whh, bhh, out);
}